// round 9
// baseline (speedup 1.0000x reference)
#include <cuda_runtime.h>
#include <cooperative_groups.h>
#include <math.h>
#include <stdint.h>

namespace cg = cooperative_groups;

#define T_STEPS 32768
#define DIM 256
#define G3 768            // 3*DIM
#define FFN_DIM 1024
#define NC 8              // scan cluster size
#define TX_BYTES 1024     // per-step bytes into each CTA: 8 CTAs * 32 lanes * 4B
#define NBANDS 256        // 32768 / 128
#define WORKERS 112

// ---------------- scratch (static device allocations) ---------------------------
__device__ float g_xg[T_STEPS * G3];
__device__ float g_ys[T_STEPS * DIM];
__device__ float g_t1[T_STEPS * FFN_DIM];
__device__ int   g_progress;          // bands of ys ready (with slack)

// ---------------- packed f32x2 helpers ------------------------------------------
__device__ __forceinline__ unsigned long long pack2(float lo, float hi) {
    unsigned long long r;
    asm("mov.b64 %0, {%1, %2};" : "=l"(r) : "f"(lo), "f"(hi));
    return r;
}
__device__ __forceinline__ unsigned long long dup2(float v) {
    unsigned long long r;
    asm("mov.b64 %0, {%1, %1};" : "=l"(r) : "f"(v));
    return r;
}
__device__ __forceinline__ void fma2(unsigned long long& acc,
                                     unsigned long long a, unsigned long long b) {
    asm("fma.rn.f32x2 %0, %1, %2, %0;" : "+l"(acc) : "l"(a), "l"(b));
}
__device__ __forceinline__ unsigned long long add2(unsigned long long a,
                                                   unsigned long long b) {
    unsigned long long r;
    asm("add.rn.f32x2 %0, %1, %2;" : "=l"(r) : "l"(a), "l"(b));
    return r;
}
__device__ __forceinline__ float hsum2(unsigned long long v) {
    float lo, hi;
    asm("mov.b64 {%0, %1}, %2;" : "=f"(lo), "=f"(hi) : "l"(v));
    return lo + hi;
}
__device__ __forceinline__ void unpack2(unsigned long long v, float& lo, float& hi) {
    asm("mov.b64 {%0, %1}, %2;" : "=f"(lo), "=f"(hi) : "l"(v));
}

// ---------------- fast transcendentals ------------------------------------------
__device__ __forceinline__ float sigmoid_fast(float x) {
    return __fdividef(1.f, 1.f + __expf(-x));
}
__device__ __forceinline__ float tanh_fast(float x) {
    float e = __expf(2.f * x);
    return 1.f - __fdividef(2.f, e + 1.f);
}

// ---------------- global flag helpers -------------------------------------------
__device__ __forceinline__ int ld_acq(const int* p) {
    int v;
    asm volatile("ld.acquire.gpu.global.b32 %0, [%1];" : "=r"(v) : "l"(p) : "memory");
    return v;
}
__device__ __forceinline__ void st_rel(int* p, int v) {
    asm volatile("st.release.gpu.global.b32 [%0], %1;" :: "l"(p), "r"(v) : "memory");
}

// ---------------- smem / cluster primitives --------------------------------------
__device__ __forceinline__ uint32_t smem_u32(const void* p) {
    uint32_t a;
    asm("{ .reg .u64 t; cvta.to.shared.u64 t, %1; cvt.u32.u64 %0, t; }"
        : "=r"(a) : "l"(p));
    return a;
}
__device__ __forceinline__ uint32_t mapa_u32(uint32_t laddr, uint32_t rank) {
    uint32_t r;
    asm("mapa.shared::cluster.u32 %0, %1, %2;" : "=r"(r) : "r"(laddr), "r"(rank));
    return r;
}
__device__ __forceinline__ void mbar_init(uint32_t mbar, uint32_t count) {
    asm volatile("mbarrier.init.shared.b64 [%0], %1;" :: "r"(mbar), "r"(count) : "memory");
}
__device__ __forceinline__ void mbar_arrive_expect_tx(uint32_t mbar, uint32_t bytes) {
    asm volatile("mbarrier.arrive.expect_tx.shared.b64 _, [%0], %1;"
                 :: "r"(mbar), "r"(bytes) : "memory");
}
__device__ __forceinline__ void mbar_wait_parity_acq(uint32_t mbar, uint32_t parity) {
    asm volatile(
        "{\n\t.reg .pred P;\n\t"
        "WL_%=:\n\t"
        "mbarrier.try_wait.parity.acquire.cluster.shared::cta.b64 P, [%0], %1, 0x989680;\n\t"
        "@P bra.uni WD_%=;\n\t"
        "bra.uni WL_%=;\n\t"
        "WD_%=:\n\t}"
        :: "r"(mbar), "r"(parity) : "memory");
}
__device__ __forceinline__ void st_async_b32(uint32_t raddr, float v, uint32_t rmbar) {
    asm volatile(
        "st.async.shared::cluster.mbarrier::complete_tx::bytes.b32 [%0], %1, [%2];"
        :: "r"(raddr), "f"(v), "r"(rmbar) : "memory");
}
__device__ __forceinline__ void cluster_arrive_rel() {
    asm volatile("barrier.cluster.arrive.aligned;" ::: "memory");
}
__device__ __forceinline__ void cluster_wait_acq() {
    asm volatile("barrier.cluster.wait.aligned;" ::: "memory");
}

// ================================================================================
// init: reset the progress flag (must run each graph replay)
// ================================================================================
__global__ void init_kernel() { g_progress = 0; }

// ================================================================================
// GRU scan: 8-CTA cluster (round-6/7 proven protocol) + progress publishing +
// early PDL trigger so the worker kernel can overlap.
// ================================================================================
__global__ void __launch_bounds__(256, 1)
scan_kernel(const float* __restrict__ Wh, const float* __restrict__ bh,
            const float* __restrict__ h0)
{
#if __CUDA_ARCH__ >= 900
    if (threadIdx.x == 0) cudaTriggerProgrammaticLaunchCompletion();
#endif
    cg::cluster_group cluster = cg::this_cluster();
    const unsigned crank = cluster.block_rank();

    __shared__ __align__(16) float h_s[2][DIM];
    __shared__ __align__(8) unsigned long long mbar[2];

    const int tid   = threadIdx.x;
    const int m_loc = tid >> 3;      // 0..31
    const int q     = tid & 7;       // k-chunk 0..7 (32 floats each)
    const int hbase = (int)crank * 32;

    const uint32_t mbar0 = smem_u32(&mbar[0]);
    if (tid == 0) { mbar_init(mbar0, 1); mbar_init(mbar0 + 8, 1); }

    // ---- 96 weights/thread: 3 gates x 32 k (chunk q), rotated sub-chunk order ---
    unsigned long long w2[3][16];
#pragma unroll
    for (int j = 0; j < 8; ++j) {
        const int c = (j + q) & 7;
        const int k = q * 32 + c * 4;
#pragma unroll
        for (int g = 0; g < 3; ++g) {
            const int gcol = g * DIM + hbase + m_loc;
            w2[g][2 * j]     = pack2(Wh[(k + 0) * G3 + gcol], Wh[(k + 1) * G3 + gcol]);
            w2[g][2 * j + 1] = pack2(Wh[(k + 2) * G3 + gcol], Wh[(k + 3) * G3 + gcol]);
        }
    }
    float bcol[3];
#pragma unroll
    for (int g = 0; g < 3; ++g) bcol[g] = bh[g * DIM + hbase + m_loc];

    for (int i = tid; i < DIM; i += 256) h_s[0][i] = h0[i];

    const bool is_gate = (q == 0);
    float xr = 0.f, xz = 0.f, xn = 0.f;
    uint32_t rdata[NC], rmbar[NC];
    if (is_gate) {
        const float* p = g_xg + hbase + m_loc;
        xr = p[0]; xz = p[DIM]; xn = p[2 * DIM];
        const uint32_t ldata = smem_u32(&h_s[0][hbase + m_loc]);
#pragma unroll
        for (int d = 0; d < NC; ++d) {
            rdata[d] = mapa_u32(ldata, (uint32_t)d);
            rmbar[d] = mapa_u32(mbar0, (uint32_t)d);
        }
    }

    cluster.sync();   // mbarrier inits + h_s[0] visible cluster-wide

#pragma unroll 1
    for (int t = 0; t < T_STEPS; ++t) {
        const int b = t & 1;
        if (t > 0)
            mbar_wait_parity_acq(mbar0 + (uint32_t)(b * 8), (uint32_t)(((t - 1) >> 1) & 1));
        if (tid == 0 && t + 1 < T_STEPS)
            mbar_arrive_expect_tx(mbar0 + (uint32_t)(((t + 1) & 1) * 8), TX_BYTES);

        // ---- 3-gate partial dot over chunk q ----
        const ulonglong2* hb = (const ulonglong2*)(h_s[b]) + q * 8;
        unsigned long long aA[3] = {0ull, 0ull, 0ull};
        unsigned long long aB[3] = {0ull, 0ull, 0ull};
#pragma unroll
        for (int j = 0; j < 8; ++j) {
            const ulonglong2 hv = hb[(j + q) & 7];
#pragma unroll
            for (int g = 0; g < 3; ++g) {
                fma2(aA[g], w2[g][2 * j], hv.x);
                fma2(aB[g], w2[g][2 * j + 1], hv.y);
            }
        }
        float s[3];
#pragma unroll
        for (int g = 0; g < 3; ++g) s[g] = hsum2(add2(aA[g], aB[g]));
#pragma unroll
        for (int off = 4; off > 0; off >>= 1)
#pragma unroll
            for (int g = 0; g < 3; ++g)
                s[g] += __shfl_down_sync(0xffffffffu, s[g], off);

        // ---- gates + async broadcast (q==0 lanes) ----
        if (is_gate) {
            const float r  = sigmoid_fast(xr + s[0] + bcol[0]);
            const float z  = sigmoid_fast(xz + s[1] + bcol[1]);
            const float hn = s[2] + bcol[2];
            const float nn = tanh_fast(xn + r * hn);
            const float hold = h_s[b][hbase + m_loc];
            const float hnew = (1.f - z) * nn + z * hold;

            if (t + 1 < T_STEPS) {
                const uint32_t boff = (uint32_t)(((t + 1) & 1) * (DIM * 4));
                const uint32_t moff = (uint32_t)(((t + 1) & 1) * 8);
#pragma unroll
                for (int d = 0; d < NC; ++d)
                    st_async_b32(rdata[d] + boff, hnew, rmbar[d] + moff);
            }

            g_ys[t * DIM + hbase + m_loc] = hnew;
            if (t + 1 < T_STEPS) {
                const float* p = g_xg + (t + 1) * G3 + hbase + m_loc;
                xr = p[0]; xz = p[DIM]; xn = p[2 * DIM];
            }
            // publish ys-band progress, 2-band slack for cross-CTA visibility
            if (crank == 0 && tid == 0 && (t & 127) == 127 && t >= 383)
                st_rel(&g_progress, ((t + 1) >> 7) - 2);
        }
    }

    cluster_arrive_rel();
    cluster_wait_acq();
    if (crank == 0 && tid == 0) st_rel(&g_progress, NBANDS);
}

// ================================================================================
// fp32 tiled GEMM (gemm1 only): f32x2 inner + reg double-buffered global loads.
// ================================================================================
__global__ __launch_bounds__(256)
void gemm_kernel(const float* __restrict__ A, const float* __restrict__ B,
                 const float* __restrict__ bias, float* __restrict__ C,
                 int M, int N, int K, int reluA, int reluOut)
{
    constexpr int BM = 128, BN = 128, BK = 8;
    __shared__ __align__(16) float As[BK][BM];
    __shared__ __align__(16) float Bs[BK][BN];

    const int tid = threadIdx.x;
    const int bm = blockIdx.y * BM;
    const int bn = blockIdx.x * BN;
    const int tx = tid & 15;
    const int ty = tid >> 4;

    const int aRow = tid >> 1;
    const int aCol = (tid & 1) * 4;
    const int bRow = tid >> 5;
    const int bCol = (tid & 31) * 4;

    const float* Aptr = A + (size_t)(bm + aRow) * K + aCol;
    const float* Bptr = B + (size_t)bRow * N + bn + bCol;

    unsigned long long acc2[8][4];
#pragma unroll
    for (int i = 0; i < 8; ++i)
#pragma unroll
        for (int j = 0; j < 4; ++j) acc2[i][j] = 0ull;

    float4 av = *(const float4*)(Aptr);
    float4 bv = *(const float4*)(Bptr);

    for (int k0 = 0; k0 < K; k0 += BK) {
        if (reluA) {
            av.x = fmaxf(av.x, 0.f); av.y = fmaxf(av.y, 0.f);
            av.z = fmaxf(av.z, 0.f); av.w = fmaxf(av.w, 0.f);
        }
        As[aCol + 0][aRow] = av.x;
        As[aCol + 1][aRow] = av.y;
        As[aCol + 2][aRow] = av.z;
        As[aCol + 3][aRow] = av.w;
        *(float4*)&Bs[bRow][bCol] = bv;
        __syncthreads();

        if (k0 + BK < K) {
            av = *(const float4*)(Aptr + k0 + BK);
            bv = *(const float4*)(Bptr + (size_t)(k0 + BK) * N);
        }

#pragma unroll
        for (int k = 0; k < BK; ++k) {
            float a[8];
            *(float4*)(a)     = *(const float4*)&As[k][ty * 8];
            *(float4*)(a + 4) = *(const float4*)&As[k][ty * 8 + 4];
            unsigned long long b2[4];
            {
                const ulonglong2 p0 = *(const ulonglong2*)&Bs[k][tx * 8];
                const ulonglong2 p1 = *(const ulonglong2*)&Bs[k][tx * 8 + 4];
                b2[0] = p0.x; b2[1] = p0.y; b2[2] = p1.x; b2[3] = p1.y;
            }
#pragma unroll
            for (int i = 0; i < 8; ++i) {
                const unsigned long long ad = dup2(a[i]);
#pragma unroll
                for (int j = 0; j < 4; ++j) fma2(acc2[i][j], ad, b2[j]);
            }
        }
        __syncthreads();
    }

#pragma unroll
    for (int i = 0; i < 8; ++i) {
        const int row = bm + ty * 8 + i;
        float* cp = C + (size_t)row * N + bn + tx * 8;
        float o[8];
#pragma unroll
        for (int j = 0; j < 4; ++j) unpack2(acc2[i][j], o[2 * j], o[2 * j + 1]);
        if (bias) {
#pragma unroll
            for (int j = 0; j < 8; ++j) o[j] += bias[bn + tx * 8 + j];
        }
        if (reluOut) {
#pragma unroll
            for (int j = 0; j < 8; ++j) o[j] = fmaxf(o[j], 0.f);
        }
        *(float4*)cp       = *(float4*)(o);
        *(float4*)(cp + 4) = *(float4*)(o + 4);
    }
}

// ================================================================================
// Worker: per-band downstream pipeline, one CTA per band, smem-resident y.
// smem layout (floats): y_s[128*260] | As[8*128] | Bs[8*128] | bg|g1|be1[256 ea]
//                       | b1[1024] | b2|g2|be2[256 ea]
// ================================================================================
#define YSTRIDE 260
#define W_Y    0
#define W_AS   (128 * YSTRIDE)
#define W_BS   (W_AS + 8 * 128)
#define W_BG   (W_BS + 8 * 128)
#define W_G1   (W_BG + 256)
#define W_BE1  (W_G1 + 256)
#define W_B1   (W_BE1 + 256)
#define W_B2   (W_B1 + 1024)
#define W_G2   (W_B2 + 256)
#define W_BE2  (W_G2 + 256)
#define W_TOTAL (W_BE2 + 256)
#define WSMEM_BYTES (W_TOTAL * 4)

// 128x128 output tile, K-loop over BK=8, A (global or smem-generic) staged via As.
__device__ __forceinline__ void gemm_tile(
    const float* __restrict__ A, int lda, int reluA,
    const float* __restrict__ B, int ldb, int K,
    float* As, float* Bs, int tid, unsigned long long acc2[8][4])
{
    const int aRow = tid >> 1;
    const int aCol = (tid & 1) * 4;
    const int bRow = tid >> 5;
    const int bCol = (tid & 31) * 4;
    const int tx = tid & 15;
    const int ty = tid >> 4;

#pragma unroll
    for (int i = 0; i < 8; ++i)
#pragma unroll
        for (int j = 0; j < 4; ++j) acc2[i][j] = 0ull;

    for (int k0 = 0; k0 < K; k0 += 8) {
        float4 av = *(const float4*)(A + (size_t)aRow * lda + k0 + aCol);
        if (reluA) {
            av.x = fmaxf(av.x, 0.f); av.y = fmaxf(av.y, 0.f);
            av.z = fmaxf(av.z, 0.f); av.w = fmaxf(av.w, 0.f);
        }
        As[(aCol + 0) * 128 + aRow] = av.x;
        As[(aCol + 1) * 128 + aRow] = av.y;
        As[(aCol + 2) * 128 + aRow] = av.z;
        As[(aCol + 3) * 128 + aRow] = av.w;
        *(float4*)&Bs[bRow * 128 + bCol] =
            *(const float4*)(B + (size_t)(k0 + bRow) * ldb + bCol);
        __syncthreads();

#pragma unroll
        for (int k = 0; k < 8; ++k) {
            float a[8];
            *(float4*)(a)     = *(const float4*)&As[k * 128 + ty * 8];
            *(float4*)(a + 4) = *(const float4*)&As[k * 128 + ty * 8 + 4];
            unsigned long long b2[4];
            {
                const ulonglong2 p0 = *(const ulonglong2*)&Bs[k * 128 + tx * 8];
                const ulonglong2 p1 = *(const ulonglong2*)&Bs[k * 128 + tx * 8 + 4];
                b2[0] = p0.x; b2[1] = p0.y; b2[2] = p1.x; b2[3] = p1.y;
            }
#pragma unroll
            for (int i = 0; i < 8; ++i) {
                const unsigned long long ad = dup2(a[i]);
#pragma unroll
                for (int j = 0; j < 4; ++j) fma2(acc2[i][j], ad, b2[j]);
            }
        }
        __syncthreads();
    }
}

// LayerNorm over 128 smem rows of 256; out==nullptr -> in place, else STG rows.
__device__ __forceinline__ void ln_rows(float* y_s, const float* g_s,
                                        const float* be_s, float* out, int tid)
{
    const int w = tid >> 5, lane = tid & 31;
    for (int r = w; r < 128; r += 8) {
        float4 v0 = *(float4*)&y_s[r * YSTRIDE + lane * 4];
        float4 v1 = *(float4*)&y_s[r * YSTRIDE + 128 + lane * 4];
        float s  = v0.x + v0.y + v0.z + v0.w + v1.x + v1.y + v1.z + v1.w;
        float ss = v0.x*v0.x + v0.y*v0.y + v0.z*v0.z + v0.w*v0.w
                 + v1.x*v1.x + v1.y*v1.y + v1.z*v1.z + v1.w*v1.w;
#pragma unroll
        for (int o = 16; o > 0; o >>= 1) {
            s  += __shfl_xor_sync(0xffffffffu, s, o);
            ss += __shfl_xor_sync(0xffffffffu, ss, o);
        }
        const float mean = s * (1.f / DIM);
        const float var  = ss * (1.f / DIM) - mean * mean;
        const float rstd = rsqrtf(var + 1e-6f);

        const float4 g0  = *(const float4*)&g_s[lane * 4];
        const float4 g1v = *(const float4*)&g_s[128 + lane * 4];
        const float4 b0  = *(const float4*)&be_s[lane * 4];
        const float4 b1v = *(const float4*)&be_s[128 + lane * 4];
        float4 o0, o1;
        o0.x = (v0.x - mean) * rstd * g0.x + b0.x;
        o0.y = (v0.y - mean) * rstd * g0.y + b0.y;
        o0.z = (v0.z - mean) * rstd * g0.z + b0.z;
        o0.w = (v0.w - mean) * rstd * g0.w + b0.w;
        o1.x = (v1.x - mean) * rstd * g1v.x + b1v.x;
        o1.y = (v1.y - mean) * rstd * g1v.y + b1v.y;
        o1.z = (v1.z - mean) * rstd * g1v.z + b1v.z;
        o1.w = (v1.w - mean) * rstd * g1v.w + b1v.w;
        if (out) {
            *(float4*)&out[r * DIM + lane * 4]       = o0;
            *(float4*)&out[r * DIM + 128 + lane * 4] = o1;
        } else {
            *(float4*)&y_s[r * YSTRIDE + lane * 4]       = o0;
            *(float4*)&y_s[r * YSTRIDE + 128 + lane * 4] = o1;
        }
    }
}

__global__ void __launch_bounds__(256, 1)
worker_kernel(const float* __restrict__ xs,
              const float* __restrict__ Wg,  const float* __restrict__ bg,
              const float* __restrict__ g1,  const float* __restrict__ be1,
              const float* __restrict__ W1,  const float* __restrict__ b1,
              const float* __restrict__ W2,  const float* __restrict__ b2,
              const float* __restrict__ g2,  const float* __restrict__ be2,
              float* __restrict__ out)
{
    extern __shared__ float ws[];
    float* y_s  = ws + W_Y;
    float* As   = ws + W_AS;
    float* Bs   = ws + W_BS;
    const int tid = threadIdx.x;
    const int tx = tid & 15;
    const int ty = tid >> 4;

    // preload parameter vectors
    {
        const int i = tid;
        if (i < 256) {
            ws[W_BG  + i] = bg[i];
            ws[W_G1  + i] = g1[i];
            ws[W_BE1 + i] = be1[i];
            ws[W_B2  + i] = b2[i];
            ws[W_G2  + i] = g2[i];
            ws[W_BE2 + i] = be2[i];
        }
        for (int k = i; k < 1024; k += 256) ws[W_B1 + k] = b1[k];
    }
    __syncthreads();

    unsigned long long acc2[8][4];

    for (int band = blockIdx.x; band < NBANDS; band += gridDim.x) {
        if (tid == 0)
            while (ld_acq(&g_progress) < band + 1) __nanosleep(1000);
        __syncthreads();

        const int row0 = band * 128;

        // ---- stage A: t3 = relu(ys)@Wg + bg ; u = xs + t3 -> y_s ----
        for (int nt = 0; nt < 2; ++nt) {
            gemm_tile(g_ys + (size_t)row0 * DIM, DIM, 1, Wg + nt * 128, DIM, DIM,
                      As, Bs, tid, acc2);
#pragma unroll
            for (int i = 0; i < 8; ++i) {
                const int r = ty * 8 + i;
                float o[8];
#pragma unroll
                for (int j = 0; j < 4; ++j) unpack2(acc2[i][j], o[2 * j], o[2 * j + 1]);
                const float* xsp = xs + (size_t)(row0 + r) * DIM + nt * 128 + tx * 8;
                const float4 x0 = *(const float4*)xsp;
                const float4 x1 = *(const float4*)(xsp + 4);
                const float* bgp = &ws[W_BG + nt * 128 + tx * 8];
                o[0] += bgp[0] + x0.x; o[1] += bgp[1] + x0.y;
                o[2] += bgp[2] + x0.z; o[3] += bgp[3] + x0.w;
                o[4] += bgp[4] + x1.x; o[5] += bgp[5] + x1.y;
                o[6] += bgp[6] + x1.z; o[7] += bgp[7] + x1.w;
                float* yp = &y_s[r * YSTRIDE + nt * 128 + tx * 8];
                *(float4*)yp       = *(float4*)(o);
                *(float4*)(yp + 4) = *(float4*)(o + 4);
            }
            __syncthreads();
        }

        // ---- stage B: y = LN1(u) in place ----
        ln_rows(y_s, ws + W_G1, ws + W_BE1, nullptr, tid);
        __syncthreads();

        // ---- stage C: t1 = relu(y @ W1 + b1) -> g_t1 ----
        for (int nt = 0; nt < 8; ++nt) {
            gemm_tile(y_s, YSTRIDE, 0, W1 + nt * 128, FFN_DIM, DIM,
                      As, Bs, tid, acc2);
#pragma unroll
            for (int i = 0; i < 8; ++i) {
                const int r = ty * 8 + i;
                float o[8];
#pragma unroll
                for (int j = 0; j < 4; ++j) unpack2(acc2[i][j], o[2 * j], o[2 * j + 1]);
                const float* b1p = &ws[W_B1 + nt * 128 + tx * 8];
#pragma unroll
                for (int j = 0; j < 8; ++j) o[j] = fmaxf(o[j] + b1p[j], 0.f);
                float* tp = g_t1 + (size_t)(row0 + r) * FFN_DIM + nt * 128 + tx * 8;
                *(float4*)tp       = *(float4*)(o);
                *(float4*)(tp + 4) = *(float4*)(o + 4);
            }
            __syncthreads();
        }

        // ---- stage D: t6 = t1 @ W2 + b2 ; u2 = y + t6 -> y_s ----
        for (int nt = 0; nt < 2; ++nt) {
            gemm_tile(g_t1 + (size_t)row0 * FFN_DIM, FFN_DIM, 0, W2 + nt * 128, DIM,
                      FFN_DIM, As, Bs, tid, acc2);
#pragma unroll
            for (int i = 0; i < 8; ++i) {
                const int r = ty * 8 + i;
                float o[8];
#pragma unroll
                for (int j = 0; j < 4; ++j) unpack2(acc2[i][j], o[2 * j], o[2 * j + 1]);
                const float* b2p = &ws[W_B2 + nt * 128 + tx * 8];
                float* yp = &y_s[r * YSTRIDE + nt * 128 + tx * 8];
#pragma unroll
                for (int j = 0; j < 8; ++j) o[j] += b2p[j] + yp[j];
                *(float4*)yp       = *(float4*)(o);
                *(float4*)(yp + 4) = *(float4*)(o + 4);
            }
            __syncthreads();
        }

        // ---- stage E: out = LN2(u2) ----
        ln_rows(y_s, ws + W_G2, ws + W_BE2, out + (size_t)row0 * DIM, tid);
        __syncthreads();
    }
}

// ================================================================================
extern "C" void kernel_launch(void* const* d_in, const int* in_sizes, int n_in,
                              void* d_out, int out_size)
{
    (void)in_sizes; (void)n_in; (void)out_size;
    const float* xs  = (const float*)d_in[0];
    const float* h0  = (const float*)d_in[1];
    const float* Wi  = (const float*)d_in[2];
    const float* Wh  = (const float*)d_in[3];
    const float* bh  = (const float*)d_in[4];
    const float* Wg  = (const float*)d_in[5];
    const float* bg  = (const float*)d_in[6];
    const float* g1  = (const float*)d_in[7];
    const float* be1 = (const float*)d_in[8];
    const float* W1  = (const float*)d_in[9];
    const float* b1  = (const float*)d_in[10];
    const float* W2  = (const float*)d_in[11];
    const float* b2  = (const float*)d_in[12];
    const float* g2  = (const float*)d_in[13];
    const float* be2 = (const float*)d_in[14];
    float* out = (float*)d_out;

    float* xg;
    cudaGetSymbolAddress((void**)&xg, g_xg);

    cudaFuncSetAttribute(worker_kernel,
                         cudaFuncAttributeMaxDynamicSharedMemorySize, WSMEM_BYTES);

    // 0) reset progress flag (must be inside the graph for replays)
    init_kernel<<<1, 1>>>();

    // 1) xg = xs @ Wi (plain — completes before the scan starts)
    gemm_kernel<<<dim3(G3 / 128, T_STEPS / 128), 256>>>(xs, Wi, nullptr, xg,
                                                        T_STEPS, G3, DIM, 0, 0);

    // 2) GRU scan (8-CTA cluster); triggers PDL completion at entry
    {
        cudaLaunchAttribute a[1];
        a[0].id = cudaLaunchAttributeClusterDimension;
        a[0].val.clusterDim.x = NC; a[0].val.clusterDim.y = 1; a[0].val.clusterDim.z = 1;
        cudaLaunchConfig_t cfg = {};
        cfg.gridDim = dim3(NC, 1, 1);
        cfg.blockDim = dim3(256, 1, 1);
        cfg.attrs = a; cfg.numAttrs = 1;
        cudaLaunchKernelEx(&cfg, scan_kernel, Wh, bh, h0);
    }

    // 3) worker pipeline, overlapped with the scan via PDL (fallback: plain)
    {
        cudaLaunchAttribute a[1];
        a[0].id = cudaLaunchAttributeProgrammaticStreamSerialization;
        a[0].val.programmaticStreamSerializationAllowed = 1;
        cudaLaunchConfig_t cfg = {};
        cfg.gridDim = dim3(WORKERS, 1, 1);
        cfg.blockDim = dim3(256, 1, 1);
        cfg.dynamicSmemBytes = WSMEM_BYTES;
        cfg.attrs = a; cfg.numAttrs = 1;
        cudaError_t e = cudaLaunchKernelEx(&cfg, worker_kernel,
                                           xs, Wg, bg, g1, be1, W1, b1, W2, b2,
                                           g2, be2, out);
        if (e != cudaSuccess) {
            (void)cudaGetLastError();
            cfg.attrs = nullptr; cfg.numAttrs = 0;   // serial fallback (still correct)
            cudaLaunchKernelEx(&cfg, worker_kernel,
                               xs, Wg, bg, g1, be1, W1, b1, W2, b2, g2, be2, out);
        }
    }
}

// round 10
// speedup vs baseline: 1.1191x; 1.1191x over previous
#include <cuda_runtime.h>
#include <cooperative_groups.h>
#include <math.h>
#include <stdint.h>

namespace cg = cooperative_groups;

#define T_STEPS 32768
#define DIM 256
#define G3 768            // 3*DIM
#define FFN_DIM 1024
#define NC 8              // scan cluster size
#define TX_BYTES 1024     // per-step bytes into each CTA: 8 CTAs * 32 lanes * 4B

// ---------------- scratch (static device allocations; no cudaMalloc allowed) ----
__device__ float g_xg[T_STEPS * G3];
__device__ float g_ys[T_STEPS * DIM];
__device__ float g_t3[T_STEPS * DIM];
__device__ float g_y [T_STEPS * DIM];
__device__ float g_t1[T_STEPS * FFN_DIM];
__device__ float g_t6[T_STEPS * DIM];

// ---------------- packed f32x2 helpers ------------------------------------------
__device__ __forceinline__ unsigned long long pack2(float lo, float hi) {
    unsigned long long r;
    asm("mov.b64 %0, {%1, %2};" : "=l"(r) : "f"(lo), "f"(hi));
    return r;
}
__device__ __forceinline__ unsigned long long dup2(float v) {
    unsigned long long r;
    asm("mov.b64 %0, {%1, %1};" : "=l"(r) : "f"(v));
    return r;
}
__device__ __forceinline__ void fma2(unsigned long long& acc,
                                     unsigned long long a, unsigned long long b) {
    asm("fma.rn.f32x2 %0, %1, %2, %0;" : "+l"(acc) : "l"(a), "l"(b));
}
__device__ __forceinline__ unsigned long long add2(unsigned long long a,
                                                   unsigned long long b) {
    unsigned long long r;
    asm("add.rn.f32x2 %0, %1, %2;" : "=l"(r) : "l"(a), "l"(b));
    return r;
}
__device__ __forceinline__ float hsum2(unsigned long long v) {
    float lo, hi;
    asm("mov.b64 {%0, %1}, %2;" : "=f"(lo), "=f"(hi) : "l"(v));
    return lo + hi;
}
__device__ __forceinline__ void unpack2(unsigned long long v, float& lo, float& hi) {
    asm("mov.b64 {%0, %1}, %2;" : "=f"(lo), "=f"(hi) : "l"(v));
}

// ---------------- fast transcendentals ------------------------------------------
__device__ __forceinline__ float sigmoid_fast(float x) {
    return __fdividef(1.f, 1.f + __expf(-x));
}
__device__ __forceinline__ float tanh_fast(float x) {
    float e = __expf(2.f * x);
    return 1.f - __fdividef(2.f, e + 1.f);
}

// ---------------- smem / cluster primitives --------------------------------------
__device__ __forceinline__ uint32_t smem_u32(const void* p) {
    uint32_t a;
    asm("{ .reg .u64 t; cvta.to.shared.u64 t, %1; cvt.u32.u64 %0, t; }"
        : "=r"(a) : "l"(p));
    return a;
}
__device__ __forceinline__ uint32_t mapa_u32(uint32_t laddr, uint32_t rank) {
    uint32_t r;
    asm("mapa.shared::cluster.u32 %0, %1, %2;" : "=r"(r) : "r"(laddr), "r"(rank));
    return r;
}
__device__ __forceinline__ void mbar_init(uint32_t mbar, uint32_t count) {
    asm volatile("mbarrier.init.shared.b64 [%0], %1;" :: "r"(mbar), "r"(count) : "memory");
}
__device__ __forceinline__ void mbar_arrive_expect_tx(uint32_t mbar, uint32_t bytes) {
    asm volatile("mbarrier.arrive.expect_tx.shared.b64 _, [%0], %1;"
                 :: "r"(mbar), "r"(bytes) : "memory");
}
__device__ __forceinline__ void mbar_wait_parity_acq(uint32_t mbar, uint32_t parity) {
    asm volatile(
        "{\n\t.reg .pred P;\n\t"
        "WL_%=:\n\t"
        "mbarrier.try_wait.parity.acquire.cluster.shared::cta.b64 P, [%0], %1, 0x989680;\n\t"
        "@P bra.uni WD_%=;\n\t"
        "bra.uni WL_%=;\n\t"
        "WD_%=:\n\t}"
        :: "r"(mbar), "r"(parity) : "memory");
}
__device__ __forceinline__ void st_async_b32(uint32_t raddr, float v, uint32_t rmbar) {
    asm volatile(
        "st.async.shared::cluster.mbarrier::complete_tx::bytes.b32 [%0], %1, [%2];"
        :: "r"(raddr), "f"(v), "r"(rmbar) : "memory");
}
__device__ __forceinline__ void cluster_arrive_rel() {
    asm volatile("barrier.cluster.arrive.aligned;" ::: "memory");
}
__device__ __forceinline__ void cluster_wait_acq() {
    asm volatile("barrier.cluster.wait.aligned;" ::: "memory");
}

// ================================================================================
// GRU scan: 8-CTA cluster (round-7 proven version). Thread (m, q) computes the
// r/z/n partial dots for h-element m over k-chunk q; intra-warp reduce; lane
// q==0 does gates + st.async broadcast. Step sync = tx-counting mbarrier.
// ================================================================================
__global__ void __cluster_dims__(NC, 1, 1) __launch_bounds__(256, 1)
scan_kernel(const float* __restrict__ Wh, const float* __restrict__ bh,
            const float* __restrict__ h0)
{
    cg::cluster_group cluster = cg::this_cluster();
    const unsigned crank = cluster.block_rank();

    __shared__ __align__(16) float h_s[2][DIM];
    __shared__ __align__(8) unsigned long long mbar[2];

    const int tid   = threadIdx.x;
    const int m_loc = tid >> 3;      // 0..31
    const int q     = tid & 7;       // k-chunk 0..7 (32 floats each)
    const int hbase = (int)crank * 32;

    const uint32_t mbar0 = smem_u32(&mbar[0]);
    if (tid == 0) { mbar_init(mbar0, 1); mbar_init(mbar0 + 8, 1); }

    // ---- 96 weights/thread: 3 gates x 32 k (chunk q), rotated sub-chunk order ---
    unsigned long long w2[3][16];
#pragma unroll
    for (int j = 0; j < 8; ++j) {
        const int c = (j + q) & 7;
        const int k = q * 32 + c * 4;
#pragma unroll
        for (int g = 0; g < 3; ++g) {
            const int gcol = g * DIM + hbase + m_loc;
            w2[g][2 * j]     = pack2(Wh[(k + 0) * G3 + gcol], Wh[(k + 1) * G3 + gcol]);
            w2[g][2 * j + 1] = pack2(Wh[(k + 2) * G3 + gcol], Wh[(k + 3) * G3 + gcol]);
        }
    }
    float bcol[3];
#pragma unroll
    for (int g = 0; g < 3; ++g) bcol[g] = bh[g * DIM + hbase + m_loc];

    for (int i = tid; i < DIM; i += 256) h_s[0][i] = h0[i];

    const bool is_gate = (q == 0);
    float xr = 0.f, xz = 0.f, xn = 0.f;
    uint32_t rdata[NC], rmbar[NC];
    if (is_gate) {
        const float* p = g_xg + hbase + m_loc;
        xr = p[0]; xz = p[DIM]; xn = p[2 * DIM];
        const uint32_t ldata = smem_u32(&h_s[0][hbase + m_loc]);
#pragma unroll
        for (int d = 0; d < NC; ++d) {
            rdata[d] = mapa_u32(ldata, (uint32_t)d);
            rmbar[d] = mapa_u32(mbar0, (uint32_t)d);
        }
    }

    cluster.sync();   // mbarrier inits + h_s[0] visible cluster-wide

#pragma unroll 1
    for (int t = 0; t < T_STEPS; ++t) {
        const int b = t & 1;
        if (t > 0)
            mbar_wait_parity_acq(mbar0 + (uint32_t)(b * 8), (uint32_t)(((t - 1) >> 1) & 1));
        if (tid == 0 && t + 1 < T_STEPS)
            mbar_arrive_expect_tx(mbar0 + (uint32_t)(((t + 1) & 1) * 8), TX_BYTES);

        // ---- 3-gate partial dot over chunk q (rotation -> conflict-free LDS) ----
        const ulonglong2* hb = (const ulonglong2*)(h_s[b]) + q * 8;
        unsigned long long aA[3] = {0ull, 0ull, 0ull};
        unsigned long long aB[3] = {0ull, 0ull, 0ull};
#pragma unroll
        for (int j = 0; j < 8; ++j) {
            const ulonglong2 hv = hb[(j + q) & 7];
#pragma unroll
            for (int g = 0; g < 3; ++g) {
                fma2(aA[g], w2[g][2 * j], hv.x);
                fma2(aB[g], w2[g][2 * j + 1], hv.y);
            }
        }
        float s[3];
#pragma unroll
        for (int g = 0; g < 3; ++g) s[g] = hsum2(add2(aA[g], aB[g]));
#pragma unroll
        for (int off = 4; off > 0; off >>= 1)
#pragma unroll
            for (int g = 0; g < 3; ++g)
                s[g] += __shfl_down_sync(0xffffffffu, s[g], off);

        // ---- gates + async broadcast (q==0 lanes only) ----
        if (is_gate) {
            const float r  = sigmoid_fast(xr + s[0] + bcol[0]);
            const float z  = sigmoid_fast(xz + s[1] + bcol[1]);
            const float hn = s[2] + bcol[2];
            const float nn = tanh_fast(xn + r * hn);
            const float hold = h_s[b][hbase + m_loc];
            const float hnew = (1.f - z) * nn + z * hold;

            if (t + 1 < T_STEPS) {
                const uint32_t boff = (uint32_t)(((t + 1) & 1) * (DIM * 4));
                const uint32_t moff = (uint32_t)(((t + 1) & 1) * 8);
#pragma unroll
                for (int d = 0; d < NC; ++d)
                    st_async_b32(rdata[d] + boff, hnew, rmbar[d] + moff);
            }

            g_ys[t * DIM + hbase + m_loc] = hnew;
            if (t + 1 < T_STEPS) {
                const float* p = g_xg + (t + 1) * G3 + hbase + m_loc;
                xr = p[0]; xz = p[DIM]; xn = p[2 * DIM];
            }
        }
    }

    cluster_arrive_rel();
    cluster_wait_acq();
}

// ================================================================================
// fp32 tiled GEMM v2: BM=BN=128, BK=16, 256 threads, 8x8 micro-tile, f32x2 FMA,
// double-buffered smem with ONE __syncthreads per k-tile.
//   A per thread: row aRow=tid>>1, cols c0=(tid&1)*8 .. +7  (2 LDG.128, 8 STS.32 transposed)
//   B per thread: row bRow=tid>>4, cols bc=(tid&15)*8 .. +7 (2 LDG.128, 2 STS.128)
// ================================================================================
__global__ __launch_bounds__(256, 2)
void gemm_kernel(const float* __restrict__ A, const float* __restrict__ B,
                 const float* __restrict__ bias, float* __restrict__ C,
                 int M, int N, int K, int reluA, int reluOut)
{
    constexpr int BM = 128, BN = 128, BK = 16;
    __shared__ __align__(16) float As[2][BK][BM];   // 16 KB
    __shared__ __align__(16) float Bs[2][BK][BN];   // 16 KB

    const int tid = threadIdx.x;
    const int bm = blockIdx.y * BM;
    const int bn = blockIdx.x * BN;
    const int tx = tid & 15;
    const int ty = tid >> 4;

    const int aRow = tid >> 1;
    const int ac0  = (tid & 1) * 8;
    const int bRow = tid >> 4;          // 0..15
    const int bc0  = (tid & 15) * 8;

    const float* Aptr = A + (size_t)(bm + aRow) * K + ac0;
    const float* Bptr = B + (size_t)bRow * N + bn + bc0;

    unsigned long long acc2[8][4];
#pragma unroll
    for (int i = 0; i < 8; ++i)
#pragma unroll
        for (int j = 0; j < 4; ++j) acc2[i][j] = 0ull;

    // ---- prologue: tile 0 -> buffer 0 ----
    float4 av0 = *(const float4*)(Aptr);
    float4 av1 = *(const float4*)(Aptr + 4);
    float4 bv0 = *(const float4*)(Bptr);
    float4 bv1 = *(const float4*)(Bptr + 4);
    if (reluA) {
        av0.x = fmaxf(av0.x, 0.f); av0.y = fmaxf(av0.y, 0.f);
        av0.z = fmaxf(av0.z, 0.f); av0.w = fmaxf(av0.w, 0.f);
        av1.x = fmaxf(av1.x, 0.f); av1.y = fmaxf(av1.y, 0.f);
        av1.z = fmaxf(av1.z, 0.f); av1.w = fmaxf(av1.w, 0.f);
    }
    As[0][ac0 + 0][aRow] = av0.x; As[0][ac0 + 1][aRow] = av0.y;
    As[0][ac0 + 2][aRow] = av0.z; As[0][ac0 + 3][aRow] = av0.w;
    As[0][ac0 + 4][aRow] = av1.x; As[0][ac0 + 5][aRow] = av1.y;
    As[0][ac0 + 6][aRow] = av1.z; As[0][ac0 + 7][aRow] = av1.w;
    *(float4*)&Bs[0][bRow][bc0]     = bv0;
    *(float4*)&Bs[0][bRow][bc0 + 4] = bv1;
    __syncthreads();

    int buf = 0;
    for (int k0 = 0; k0 < K; k0 += BK) {
        const bool has_next = (k0 + BK) < K;
        if (has_next) {   // issue next tile's global loads (covered by compute)
            av0 = *(const float4*)(Aptr + k0 + BK);
            av1 = *(const float4*)(Aptr + k0 + BK + 4);
            bv0 = *(const float4*)(Bptr + (size_t)(k0 + BK) * N);
            bv1 = *(const float4*)(Bptr + (size_t)(k0 + BK) * N + 4);
        }

#pragma unroll
        for (int k = 0; k < BK; ++k) {
            float a[8];
            *(float4*)(a)     = *(const float4*)&As[buf][k][ty * 8];
            *(float4*)(a + 4) = *(const float4*)&As[buf][k][ty * 8 + 4];
            unsigned long long b2[4];
            {
                const ulonglong2 p0 = *(const ulonglong2*)&Bs[buf][k][tx * 8];
                const ulonglong2 p1 = *(const ulonglong2*)&Bs[buf][k][tx * 8 + 4];
                b2[0] = p0.x; b2[1] = p0.y; b2[2] = p1.x; b2[3] = p1.y;
            }
#pragma unroll
            for (int i = 0; i < 8; ++i) {
                const unsigned long long ad = dup2(a[i]);
#pragma unroll
                for (int j = 0; j < 4; ++j) fma2(acc2[i][j], ad, b2[j]);
            }
        }

        if (has_next) {
            const int nb = buf ^ 1;
            if (reluA) {
                av0.x = fmaxf(av0.x, 0.f); av0.y = fmaxf(av0.y, 0.f);
                av0.z = fmaxf(av0.z, 0.f); av0.w = fmaxf(av0.w, 0.f);
                av1.x = fmaxf(av1.x, 0.f); av1.y = fmaxf(av1.y, 0.f);
                av1.z = fmaxf(av1.z, 0.f); av1.w = fmaxf(av1.w, 0.f);
            }
            As[nb][ac0 + 0][aRow] = av0.x; As[nb][ac0 + 1][aRow] = av0.y;
            As[nb][ac0 + 2][aRow] = av0.z; As[nb][ac0 + 3][aRow] = av0.w;
            As[nb][ac0 + 4][aRow] = av1.x; As[nb][ac0 + 5][aRow] = av1.y;
            As[nb][ac0 + 6][aRow] = av1.z; As[nb][ac0 + 7][aRow] = av1.w;
            *(float4*)&Bs[nb][bRow][bc0]     = bv0;
            *(float4*)&Bs[nb][bRow][bc0 + 4] = bv1;
            __syncthreads();   // publish buf^1; also guarantees buf reads done
            buf = nb;
        }
    }

    float bias_r[8];
#pragma unroll
    for (int j = 0; j < 8; ++j) bias_r[j] = bias ? bias[bn + tx * 8 + j] : 0.f;

#pragma unroll
    for (int i = 0; i < 8; ++i) {
        const int row = bm + ty * 8 + i;
        float* cp = C + (size_t)row * N + bn + tx * 8;
        float o[8];
#pragma unroll
        for (int j = 0; j < 4; ++j) unpack2(acc2[i][j], o[2 * j], o[2 * j + 1]);
#pragma unroll
        for (int j = 0; j < 8; ++j) {
            float v = o[j] + bias_r[j];
            o[j] = reluOut ? fmaxf(v, 0.f) : v;
        }
        *(float4*)cp       = *(float4*)(o);
        *(float4*)(cp + 4) = *(float4*)(o + 4);
    }
}

// ================================================================================
// Fused residual + LayerNorm (rows of 256): out = LN(base + delta)*g + b
// ================================================================================
__global__ __launch_bounds__(256)
void ln_kernel(const float* __restrict__ base, const float* __restrict__ delta,
               const float* __restrict__ g, const float* __restrict__ b,
               float* __restrict__ out)
{
    const int row  = blockIdx.x * 8 + (threadIdx.x >> 5);
    const int lane = threadIdx.x & 31;

    const float4* bp = (const float4*)(base  + (size_t)row * DIM);
    const float4* dp = (const float4*)(delta + (size_t)row * DIM);
    float4 x0 = bp[lane],      d0 = dp[lane];
    float4 x1 = bp[32 + lane], d1 = dp[32 + lane];
    float4 u0, u1;
    u0.x = x0.x + d0.x; u0.y = x0.y + d0.y; u0.z = x0.z + d0.z; u0.w = x0.w + d0.w;
    u1.x = x1.x + d1.x; u1.y = x1.y + d1.y; u1.z = x1.z + d1.z; u1.w = x1.w + d1.w;

    float s  = u0.x + u0.y + u0.z + u0.w + u1.x + u1.y + u1.z + u1.w;
    float ss = u0.x*u0.x + u0.y*u0.y + u0.z*u0.z + u0.w*u0.w
             + u1.x*u1.x + u1.y*u1.y + u1.z*u1.z + u1.w*u1.w;
#pragma unroll
    for (int o = 16; o > 0; o >>= 1) {
        s  += __shfl_xor_sync(0xffffffffu, s, o);
        ss += __shfl_xor_sync(0xffffffffu, ss, o);
    }
    const float mean = s * (1.f / DIM);
    const float var  = ss * (1.f / DIM) - mean * mean;
    const float rstd = rsqrtf(var + 1e-6f);

    const float4 gv0 = ((const float4*)g)[lane];
    const float4 gv1 = ((const float4*)g)[32 + lane];
    const float4 bv0 = ((const float4*)b)[lane];
    const float4 bv1 = ((const float4*)b)[32 + lane];

    float4 o0, o1;
    o0.x = (u0.x - mean) * rstd * gv0.x + bv0.x;
    o0.y = (u0.y - mean) * rstd * gv0.y + bv0.y;
    o0.z = (u0.z - mean) * rstd * gv0.z + bv0.z;
    o0.w = (u0.w - mean) * rstd * gv0.w + bv0.w;
    o1.x = (u1.x - mean) * rstd * gv1.x + bv1.x;
    o1.y = (u1.y - mean) * rstd * gv1.y + bv1.y;
    o1.z = (u1.z - mean) * rstd * gv1.z + bv1.z;
    o1.w = (u1.w - mean) * rstd * gv1.w + bv1.w;

    float4* op = (float4*)(out + (size_t)row * DIM);
    op[lane] = o0;
    op[32 + lane] = o1;
}

// ================================================================================
extern "C" void kernel_launch(void* const* d_in, const int* in_sizes, int n_in,
                              void* d_out, int out_size)
{
    (void)in_sizes; (void)n_in; (void)out_size;
    const float* xs  = (const float*)d_in[0];
    const float* h0  = (const float*)d_in[1];
    const float* Wi  = (const float*)d_in[2];
    const float* Wh  = (const float*)d_in[3];
    const float* bh  = (const float*)d_in[4];
    const float* Wg  = (const float*)d_in[5];
    const float* bg  = (const float*)d_in[6];
    const float* g1  = (const float*)d_in[7];
    const float* be1 = (const float*)d_in[8];
    const float* W1  = (const float*)d_in[9];
    const float* b1  = (const float*)d_in[10];
    const float* W2  = (const float*)d_in[11];
    const float* b2  = (const float*)d_in[12];
    const float* g2  = (const float*)d_in[13];
    const float* be2 = (const float*)d_in[14];
    float* out = (float*)d_out;

    float *xg, *ys, *t3, *y, *t1, *t6;
    cudaGetSymbolAddress((void**)&xg, g_xg);
    cudaGetSymbolAddress((void**)&ys, g_ys);
    cudaGetSymbolAddress((void**)&t3, g_t3);
    cudaGetSymbolAddress((void**)&y,  g_y);
    cudaGetSymbolAddress((void**)&t1, g_t1);
    cudaGetSymbolAddress((void**)&t6, g_t6);

    // 1) xg = xs @ Wi
    gemm_kernel<<<dim3(G3 / 128, T_STEPS / 128), 256>>>(xs, Wi, nullptr, xg,
                                                        T_STEPS, G3, DIM, 0, 0);
    // 2) sequential GRU scan -> ys
    scan_kernel<<<NC, 256>>>(Wh, bh, h0);
    // 3) t3 = relu(ys) @ Wg + bg
    gemm_kernel<<<dim3(DIM / 128, T_STEPS / 128), 256>>>(ys, Wg, bg, t3,
                                                         T_STEPS, DIM, DIM, 1, 0);
    // 4) y = LN(xs + t3) * g1 + be1
    ln_kernel<<<T_STEPS / 8, 256>>>(xs, t3, g1, be1, y);
    // 5) t1 = relu(y @ W1 + b1)
    gemm_kernel<<<dim3(FFN_DIM / 128, T_STEPS / 128), 256>>>(y, W1, b1, t1,
                                                             T_STEPS, FFN_DIM, DIM, 0, 1);
    // 6) t6 = t1 @ W2 + b2
    gemm_kernel<<<dim3(DIM / 128, T_STEPS / 128), 256>>>(t1, W2, b2, t6,
                                                         T_STEPS, DIM, FFN_DIM, 0, 0);
    // 7) out = LN(y + t6) * g2 + be2
    ln_kernel<<<T_STEPS / 8, 256>>>(y, t6, g2, be2, out);
}

// round 12
// speedup vs baseline: 1.1239x; 1.0043x over previous
#include <cuda_runtime.h>
#include <cooperative_groups.h>
#include <math.h>
#include <stdint.h>

namespace cg = cooperative_groups;

#define T_STEPS 32768
#define DIM 256
#define G3 768            // 3*DIM
#define FFN_DIM 1024
#define NC 8              // scan cluster size
#define TX_BYTES 1024     // per-step bytes into each CTA: 8 CTAs * 32 lanes * 4B

// ---------------- scratch (static device allocations; no cudaMalloc allowed) ----
__device__ float g_xg[T_STEPS * G3];
__device__ float g_ys[T_STEPS * DIM];
__device__ float g_t3[T_STEPS * DIM];
__device__ float g_y [T_STEPS * DIM];
__device__ float g_t1[T_STEPS * FFN_DIM];
__device__ float g_t6[T_STEPS * DIM];

// ---------------- packed f32x2 helpers ------------------------------------------
__device__ __forceinline__ unsigned long long pack2(float lo, float hi) {
    unsigned long long r;
    asm("mov.b64 %0, {%1, %2};" : "=l"(r) : "f"(lo), "f"(hi));
    return r;
}
__device__ __forceinline__ unsigned long long dup2(float v) {
    unsigned long long r;
    asm("mov.b64 %0, {%1, %1};" : "=l"(r) : "f"(v));
    return r;
}
__device__ __forceinline__ void fma2(unsigned long long& acc,
                                     unsigned long long a, unsigned long long b) {
    asm("fma.rn.f32x2 %0, %1, %2, %0;" : "+l"(acc) : "l"(a), "l"(b));
}
__device__ __forceinline__ unsigned long long add2(unsigned long long a,
                                                   unsigned long long b) {
    unsigned long long r;
    asm("add.rn.f32x2 %0, %1, %2;" : "=l"(r) : "l"(a), "l"(b));
    return r;
}
__device__ __forceinline__ float hsum2(unsigned long long v) {
    float lo, hi;
    asm("mov.b64 {%0, %1}, %2;" : "=f"(lo), "=f"(hi) : "l"(v));
    return lo + hi;
}
__device__ __forceinline__ void unpack2(unsigned long long v, float& lo, float& hi) {
    asm("mov.b64 {%0, %1}, %2;" : "=f"(lo), "=f"(hi) : "l"(v));
}

// ---------------- fast transcendentals ------------------------------------------
__device__ __forceinline__ float sigmoid_fast(float x) {
    return __fdividef(1.f, 1.f + __expf(-x));
}
__device__ __forceinline__ float tanh_fast(float x) {
    float e = __expf(2.f * x);
    return 1.f - __fdividef(2.f, e + 1.f);
}

// ---------------- smem / cluster primitives --------------------------------------
__device__ __forceinline__ uint32_t smem_u32(const void* p) {
    uint32_t a;
    asm("{ .reg .u64 t; cvta.to.shared.u64 t, %1; cvt.u32.u64 %0, t; }"
        : "=r"(a) : "l"(p));
    return a;
}
__device__ __forceinline__ uint32_t mapa_u32(uint32_t laddr, uint32_t rank) {
    uint32_t r;
    asm("mapa.shared::cluster.u32 %0, %1, %2;" : "=r"(r) : "r"(laddr), "r"(rank));
    return r;
}
__device__ __forceinline__ void mbar_init(uint32_t mbar, uint32_t count) {
    asm volatile("mbarrier.init.shared.b64 [%0], %1;" :: "r"(mbar), "r"(count) : "memory");
}
__device__ __forceinline__ void mbar_arrive_expect_tx(uint32_t mbar, uint32_t bytes) {
    asm volatile("mbarrier.arrive.expect_tx.shared.b64 _, [%0], %1;"
                 :: "r"(mbar), "r"(bytes) : "memory");
}
__device__ __forceinline__ void mbar_wait_parity_acq(uint32_t mbar, uint32_t parity) {
    asm volatile(
        "{\n\t.reg .pred P;\n\t"
        "WL_%=:\n\t"
        "mbarrier.try_wait.parity.acquire.cluster.shared::cta.b64 P, [%0], %1, 0x989680;\n\t"
        "@P bra.uni WD_%=;\n\t"
        "bra.uni WL_%=;\n\t"
        "WD_%=:\n\t}"
        :: "r"(mbar), "r"(parity) : "memory");
}
__device__ __forceinline__ void st_async_b32(uint32_t raddr, float v, uint32_t rmbar) {
    asm volatile(
        "st.async.shared::cluster.mbarrier::complete_tx::bytes.b32 [%0], %1, [%2];"
        :: "r"(raddr), "f"(v), "r"(rmbar) : "memory");
}
__device__ __forceinline__ void cluster_arrive_rel() {
    asm volatile("barrier.cluster.arrive.aligned;" ::: "memory");
}
__device__ __forceinline__ void cluster_wait_acq() {
    asm volatile("barrier.cluster.wait.aligned;" ::: "memory");
}

// ================================================================================
// GRU scan: 8-CTA cluster (round-7 proven version, unchanged). Thread (m, q)
// computes r/z/n partial dots for h-element m over k-chunk q; intra-warp reduce;
// lane q==0 does gates + st.async broadcast. Step sync = tx-counting mbarrier.
// ================================================================================
__global__ void __cluster_dims__(NC, 1, 1) __launch_bounds__(256, 1)
scan_kernel(const float* __restrict__ Wh, const float* __restrict__ bh,
            const float* __restrict__ h0)
{
    cg::cluster_group cluster = cg::this_cluster();
    const unsigned crank = cluster.block_rank();

    __shared__ __align__(16) float h_s[2][DIM];
    __shared__ __align__(8) unsigned long long mbar[2];

    const int tid   = threadIdx.x;
    const int m_loc = tid >> 3;      // 0..31
    const int q     = tid & 7;       // k-chunk 0..7 (32 floats each)
    const int hbase = (int)crank * 32;

    const uint32_t mbar0 = smem_u32(&mbar[0]);
    if (tid == 0) { mbar_init(mbar0, 1); mbar_init(mbar0 + 8, 1); }

    // ---- 96 weights/thread: 3 gates x 32 k (chunk q), rotated sub-chunk order ---
    unsigned long long w2[3][16];
#pragma unroll
    for (int j = 0; j < 8; ++j) {
        const int c = (j + q) & 7;
        const int k = q * 32 + c * 4;
#pragma unroll
        for (int g = 0; g < 3; ++g) {
            const int gcol = g * DIM + hbase + m_loc;
            w2[g][2 * j]     = pack2(Wh[(k + 0) * G3 + gcol], Wh[(k + 1) * G3 + gcol]);
            w2[g][2 * j + 1] = pack2(Wh[(k + 2) * G3 + gcol], Wh[(k + 3) * G3 + gcol]);
        }
    }
    float bcol[3];
#pragma unroll
    for (int g = 0; g < 3; ++g) bcol[g] = bh[g * DIM + hbase + m_loc];

    for (int i = tid; i < DIM; i += 256) h_s[0][i] = h0[i];

    const bool is_gate = (q == 0);
    float xr = 0.f, xz = 0.f, xn = 0.f;
    uint32_t rdata[NC], rmbar[NC];
    if (is_gate) {
        const float* p = g_xg + hbase + m_loc;
        xr = p[0]; xz = p[DIM]; xn = p[2 * DIM];
        const uint32_t ldata = smem_u32(&h_s[0][hbase + m_loc]);
#pragma unroll
        for (int d = 0; d < NC; ++d) {
            rdata[d] = mapa_u32(ldata, (uint32_t)d);
            rmbar[d] = mapa_u32(mbar0, (uint32_t)d);
        }
    }

    cluster.sync();   // mbarrier inits + h_s[0] visible cluster-wide

#pragma unroll 1
    for (int t = 0; t < T_STEPS; ++t) {
        const int b = t & 1;
        if (t > 0)
            mbar_wait_parity_acq(mbar0 + (uint32_t)(b * 8), (uint32_t)(((t - 1) >> 1) & 1));
        if (tid == 0 && t + 1 < T_STEPS)
            mbar_arrive_expect_tx(mbar0 + (uint32_t)(((t + 1) & 1) * 8), TX_BYTES);

        // ---- 3-gate partial dot over chunk q (rotation -> conflict-free LDS) ----
        const ulonglong2* hb = (const ulonglong2*)(h_s[b]) + q * 8;
        unsigned long long aA[3] = {0ull, 0ull, 0ull};
        unsigned long long aB[3] = {0ull, 0ull, 0ull};
#pragma unroll
        for (int j = 0; j < 8; ++j) {
            const ulonglong2 hv = hb[(j + q) & 7];
#pragma unroll
            for (int g = 0; g < 3; ++g) {
                fma2(aA[g], w2[g][2 * j], hv.x);
                fma2(aB[g], w2[g][2 * j + 1], hv.y);
            }
        }
        float s[3];
#pragma unroll
        for (int g = 0; g < 3; ++g) s[g] = hsum2(add2(aA[g], aB[g]));
#pragma unroll
        for (int off = 4; off > 0; off >>= 1)
#pragma unroll
            for (int g = 0; g < 3; ++g)
                s[g] += __shfl_down_sync(0xffffffffu, s[g], off);

        // ---- gates + async broadcast (q==0 lanes only) ----
        if (is_gate) {
            const float r  = sigmoid_fast(xr + s[0] + bcol[0]);
            const float z  = sigmoid_fast(xz + s[1] + bcol[1]);
            const float hn = s[2] + bcol[2];
            const float nn = tanh_fast(xn + r * hn);
            const float hold = h_s[b][hbase + m_loc];
            const float hnew = (1.f - z) * nn + z * hold;

            if (t + 1 < T_STEPS) {
                const uint32_t boff = (uint32_t)(((t + 1) & 1) * (DIM * 4));
                const uint32_t moff = (uint32_t)(((t + 1) & 1) * 8);
#pragma unroll
                for (int d = 0; d < NC; ++d)
                    st_async_b32(rdata[d] + boff, hnew, rmbar[d] + moff);
            }

            g_ys[t * DIM + hbase + m_loc] = hnew;
            if (t + 1 < T_STEPS) {
                const float* p = g_xg + (t + 1) * G3 + hbase + m_loc;
                xr = p[0]; xz = p[DIM]; xn = p[2 * DIM];
            }
        }
    }

    cluster_arrive_rel();
    cluster_wait_acq();
}

// ================================================================================
// fp32 tiled GEMM v2-nocap: BM=BN=128, BK=16, 256 threads, 8x8 micro-tile,
// f32x2 FMA, double-buffered smem, ONE __syncthreads per k-tile.
// NO occupancy cap -> no register spills (round-9 bug was __launch_bounds__(256,2)
// forcing a 128-reg budget and spilling the 64-reg accumulator to local).
// ================================================================================
__global__ __launch_bounds__(256)
void gemm_kernel(const float* __restrict__ A, const float* __restrict__ B,
                 const float* __restrict__ bias, float* __restrict__ C,
                 int M, int N, int K, int reluA, int reluOut)
{
    constexpr int BM = 128, BN = 128, BK = 16;
    __shared__ __align__(16) float As[2][BK][BM];   // 16 KB
    __shared__ __align__(16) float Bs[2][BK][BN];   // 16 KB

    const int tid = threadIdx.x;
    const int bm = blockIdx.y * BM;
    const int bn = blockIdx.x * BN;
    const int tx = tid & 15;
    const int ty = tid >> 4;

    const int aRow = tid >> 1;
    const int ac0  = (tid & 1) * 8;
    const int bRow = tid >> 4;          // 0..15
    const int bc0  = (tid & 15) * 8;

    const float* Aptr = A + (size_t)(bm + aRow) * K + ac0;
    const float* Bptr = B + (size_t)bRow * N + bn + bc0;

    unsigned long long acc2[8][4];
#pragma unroll
    for (int i = 0; i < 8; ++i)
#pragma unroll
        for (int j = 0; j < 4; ++j) acc2[i][j] = 0ull;

    // ---- prologue: tile 0 -> buffer 0 ----
    float4 av0 = *(const float4*)(Aptr);
    float4 av1 = *(const float4*)(Aptr + 4);
    float4 bv0 = *(const float4*)(Bptr);
    float4 bv1 = *(const float4*)(Bptr + 4);
    if (reluA) {
        av0.x = fmaxf(av0.x, 0.f); av0.y = fmaxf(av0.y, 0.f);
        av0.z = fmaxf(av0.z, 0.f); av0.w = fmaxf(av0.w, 0.f);
        av1.x = fmaxf(av1.x, 0.f); av1.y = fmaxf(av1.y, 0.f);
        av1.z = fmaxf(av1.z, 0.f); av1.w = fmaxf(av1.w, 0.f);
    }
    As[0][ac0 + 0][aRow] = av0.x; As[0][ac0 + 1][aRow] = av0.y;
    As[0][ac0 + 2][aRow] = av0.z; As[0][ac0 + 3][aRow] = av0.w;
    As[0][ac0 + 4][aRow] = av1.x; As[0][ac0 + 5][aRow] = av1.y;
    As[0][ac0 + 6][aRow] = av1.z; As[0][ac0 + 7][aRow] = av1.w;
    *(float4*)&Bs[0][bRow][bc0]     = bv0;
    *(float4*)&Bs[0][bRow][bc0 + 4] = bv1;
    __syncthreads();

    int buf = 0;
#pragma unroll 1
    for (int k0 = 0; k0 < K; k0 += BK) {
        const bool has_next = (k0 + BK) < K;
        if (has_next) {   // issue next tile's global loads (covered by compute)
            av0 = *(const float4*)(Aptr + k0 + BK);
            av1 = *(const float4*)(Aptr + k0 + BK + 4);
            bv0 = *(const float4*)(Bptr + (size_t)(k0 + BK) * N);
            bv1 = *(const float4*)(Bptr + (size_t)(k0 + BK) * N + 4);
        }

#pragma unroll
        for (int k = 0; k < BK; ++k) {
            float a[8];
            *(float4*)(a)     = *(const float4*)&As[buf][k][ty * 8];
            *(float4*)(a + 4) = *(const float4*)&As[buf][k][ty * 8 + 4];
            unsigned long long b2[4];
            {
                const ulonglong2 p0 = *(const ulonglong2*)&Bs[buf][k][tx * 8];
                const ulonglong2 p1 = *(const ulonglong2*)&Bs[buf][k][tx * 8 + 4];
                b2[0] = p0.x; b2[1] = p0.y; b2[2] = p1.x; b2[3] = p1.y;
            }
#pragma unroll
            for (int i = 0; i < 8; ++i) {
                const unsigned long long ad = dup2(a[i]);
#pragma unroll
                for (int j = 0; j < 4; ++j) fma2(acc2[i][j], ad, b2[j]);
            }
        }

        if (has_next) {
            const int nb = buf ^ 1;
            if (reluA) {
                av0.x = fmaxf(av0.x, 0.f); av0.y = fmaxf(av0.y, 0.f);
                av0.z = fmaxf(av0.z, 0.f); av0.w = fmaxf(av0.w, 0.f);
                av1.x = fmaxf(av1.x, 0.f); av1.y = fmaxf(av1.y, 0.f);
                av1.z = fmaxf(av1.z, 0.f); av1.w = fmaxf(av1.w, 0.f);
            }
            As[nb][ac0 + 0][aRow] = av0.x; As[nb][ac0 + 1][aRow] = av0.y;
            As[nb][ac0 + 2][aRow] = av0.z; As[nb][ac0 + 3][aRow] = av0.w;
            As[nb][ac0 + 4][aRow] = av1.x; As[nb][ac0 + 5][aRow] = av1.y;
            As[nb][ac0 + 6][aRow] = av1.z; As[nb][ac0 + 7][aRow] = av1.w;
            *(float4*)&Bs[nb][bRow][bc0]     = bv0;
            *(float4*)&Bs[nb][bRow][bc0 + 4] = bv1;
            __syncthreads();   // publish buf^1; also guarantees buf reads done
            buf = nb;
        }
    }

    float bias_r[8];
#pragma unroll
    for (int j = 0; j < 8; ++j) bias_r[j] = bias ? bias[bn + tx * 8 + j] : 0.f;

#pragma unroll
    for (int i = 0; i < 8; ++i) {
        const int row = bm + ty * 8 + i;
        float* cp = C + (size_t)row * N + bn + tx * 8;
        float o[8];
#pragma unroll
        for (int j = 0; j < 4; ++j) unpack2(acc2[i][j], o[2 * j], o[2 * j + 1]);
#pragma unroll
        for (int j = 0; j < 8; ++j) {
            float v = o[j] + bias_r[j];
            o[j] = reluOut ? fmaxf(v, 0.f) : v;
        }
        *(float4*)cp       = *(float4*)(o);
        *(float4*)(cp + 4) = *(float4*)(o + 4);
    }
}

// ================================================================================
// Fused residual + LayerNorm (rows of 256): out = LN(base + delta)*g + b
// ================================================================================
__global__ __launch_bounds__(256)
void ln_kernel(const float* __restrict__ base, const float* __restrict__ delta,
               const float* __restrict__ g, const float* __restrict__ b,
               float* __restrict__ out)
{
    const int row  = blockIdx.x * 8 + (threadIdx.x >> 5);
    const int lane = threadIdx.x & 31;

    const float4* bp = (const float4*)(base  + (size_t)row * DIM);
    const float4* dp = (const float4*)(delta + (size_t)row * DIM);
    float4 x0 = bp[lane],      d0 = dp[lane];
    float4 x1 = bp[32 + lane], d1 = dp[32 + lane];
    float4 u0, u1;
    u0.x = x0.x + d0.x; u0.y = x0.y + d0.y; u0.z = x0.z + d0.z; u0.w = x0.w + d0.w;
    u1.x = x1.x + d1.x; u1.y = x1.y + d1.y; u1.z = x1.z + d1.z; u1.w = x1.w + d1.w;

    float s  = u0.x + u0.y + u0.z + u0.w + u1.x + u1.y + u1.z + u1.w;
    float ss = u0.x*u0.x + u0.y*u0.y + u0.z*u0.z + u0.w*u0.w
             + u1.x*u1.x + u1.y*u1.y + u1.z*u1.z + u1.w*u1.w;
#pragma unroll
    for (int o = 16; o > 0; o >>= 1) {
        s  += __shfl_xor_sync(0xffffffffu, s, o);
        ss += __shfl_xor_sync(0xffffffffu, ss, o);
    }
    const float mean = s * (1.f / DIM);
    const float var  = ss * (1.f / DIM) - mean * mean;
    const float rstd = rsqrtf(var + 1e-6f);

    const float4 gv0 = ((const float4*)g)[lane];
    const float4 gv1 = ((const float4*)g)[32 + lane];
    const float4 bv0 = ((const float4*)b)[lane];
    const float4 bv1 = ((const float4*)b)[32 + lane];

    float4 o0, o1;
    o0.x = (u0.x - mean) * rstd * gv0.x + bv0.x;
    o0.y = (u0.y - mean) * rstd * gv0.y + bv0.y;
    o0.z = (u0.z - mean) * rstd * gv0.z + bv0.z;
    o0.w = (u0.w - mean) * rstd * gv0.w + bv0.w;
    o1.x = (u1.x - mean) * rstd * gv1.x + bv1.x;
    o1.y = (u1.y - mean) * rstd * gv1.y + bv1.y;
    o1.z = (u1.z - mean) * rstd * gv1.z + bv1.z;
    o1.w = (u1.w - mean) * rstd * gv1.w + bv1.w;

    float4* op = (float4*)(out + (size_t)row * DIM);
    op[lane] = o0;
    op[32 + lane] = o1;
}

// ================================================================================
extern "C" void kernel_launch(void* const* d_in, const int* in_sizes, int n_in,
                              void* d_out, int out_size)
{
    (void)in_sizes; (void)n_in; (void)out_size;
    const float* xs  = (const float*)d_in[0];
    const float* h0  = (const float*)d_in[1];
    const float* Wi  = (const float*)d_in[2];
    const float* Wh  = (const float*)d_in[3];
    const float* bh  = (const float*)d_in[4];
    const float* Wg  = (const float*)d_in[5];
    const float* bg  = (const float*)d_in[6];
    const float* g1  = (const float*)d_in[7];
    const float* be1 = (const float*)d_in[8];
    const float* W1  = (const float*)d_in[9];
    const float* b1  = (const float*)d_in[10];
    const float* W2  = (const float*)d_in[11];
    const float* b2  = (const float*)d_in[12];
    const float* g2  = (const float*)d_in[13];
    const float* be2 = (const float*)d_in[14];
    float* out = (float*)d_out;

    float *xg, *ys, *t3, *y, *t1, *t6;
    cudaGetSymbolAddress((void**)&xg, g_xg);
    cudaGetSymbolAddress((void**)&ys, g_ys);
    cudaGetSymbolAddress((void**)&t3, g_t3);
    cudaGetSymbolAddress((void**)&y,  g_y);
    cudaGetSymbolAddress((void**)&t1, g_t1);
    cudaGetSymbolAddress((void**)&t6, g_t6);

    // 1) xg = xs @ Wi
    gemm_kernel<<<dim3(G3 / 128, T_STEPS / 128), 256>>>(xs, Wi, nullptr, xg,
                                                        T_STEPS, G3, DIM, 0, 0);
    // 2) sequential GRU scan -> ys
    scan_kernel<<<NC, 256>>>(Wh, bh, h0);
    // 3) t3 = relu(ys) @ Wg + bg
    gemm_kernel<<<dim3(DIM / 128, T_STEPS / 128), 256>>>(ys, Wg, bg, t3,
                                                         T_STEPS, DIM, DIM, 1, 0);
    // 4) y = LN(xs + t3) * g1 + be1
    ln_kernel<<<T_STEPS / 8, 256>>>(xs, t3, g1, be1, y);
    // 5) t1 = relu(y @ W1 + b1)
    gemm_kernel<<<dim3(FFN_DIM / 128, T_STEPS / 128), 256>>>(y, W1, b1, t1,
                                                             T_STEPS, FFN_DIM, DIM, 0, 1);
    // 6) t6 = t1 @ W2 + b2
    gemm_kernel<<<dim3(DIM / 128, T_STEPS / 128), 256>>>(t1, W2, b2, t6,
                                                         T_STEPS, DIM, FFN_DIM, 0, 0);
    // 7) out = LN(y + t6) * g2 + be2
    ln_kernel<<<T_STEPS / 8, 256>>>(y, t6, g2, be2, out);
}

// round 13
// speedup vs baseline: 1.1901x; 1.0589x over previous
#include <cuda_runtime.h>
#include <cooperative_groups.h>
#include <math.h>
#include <stdint.h>

namespace cg = cooperative_groups;

#define T_STEPS 32768
#define DIM 256
#define G3 768            // 3*DIM
#define FFN_DIM 1024
#define NC 8              // scan cluster size
#define TX_BYTES 1024     // per-step bytes into each CTA: 8 src * 32 vals * 4B

// ---------------- scratch (static device allocations; no cudaMalloc allowed) ----
__device__ float g_xg[T_STEPS * G3];
__device__ float g_ys[T_STEPS * DIM];
__device__ float g_t3[T_STEPS * DIM];
__device__ float g_y [T_STEPS * DIM];
__device__ float g_t1[T_STEPS * FFN_DIM];
__device__ float g_t6[T_STEPS * DIM];

// ---------------- packed f32x2 helpers ------------------------------------------
__device__ __forceinline__ unsigned long long pack2(float lo, float hi) {
    unsigned long long r;
    asm("mov.b64 %0, {%1, %2};" : "=l"(r) : "f"(lo), "f"(hi));
    return r;
}
__device__ __forceinline__ unsigned long long dup2(float v) {
    unsigned long long r;
    asm("mov.b64 %0, {%1, %1};" : "=l"(r) : "f"(v));
    return r;
}
__device__ __forceinline__ void fma2(unsigned long long& acc,
                                     unsigned long long a, unsigned long long b) {
    asm("fma.rn.f32x2 %0, %1, %2, %0;" : "+l"(acc) : "l"(a), "l"(b));
}
__device__ __forceinline__ unsigned long long add2(unsigned long long a,
                                                   unsigned long long b) {
    unsigned long long r;
    asm("add.rn.f32x2 %0, %1, %2;" : "=l"(r) : "l"(a), "l"(b));
    return r;
}
__device__ __forceinline__ float hsum2(unsigned long long v) {
    float lo, hi;
    asm("mov.b64 {%0, %1}, %2;" : "=f"(lo), "=f"(hi) : "l"(v));
    return lo + hi;
}

// ---------------- fast transcendentals ------------------------------------------
__device__ __forceinline__ float sigmoid_fast(float x) {
    return __fdividef(1.f, 1.f + __expf(-x));
}
__device__ __forceinline__ float tanh_fast(float x) {
    float e = __expf(2.f * x);
    return 1.f - __fdividef(2.f, e + 1.f);
}

// ---------------- smem / cluster primitives --------------------------------------
__device__ __forceinline__ uint32_t smem_u32(const void* p) {
    uint32_t a;
    asm("{ .reg .u64 t; cvta.to.shared.u64 t, %1; cvt.u32.u64 %0, t; }"
        : "=r"(a) : "l"(p));
    return a;
}
__device__ __forceinline__ uint32_t mapa_u32(uint32_t laddr, uint32_t rank) {
    uint32_t r;
    asm("mapa.shared::cluster.u32 %0, %1, %2;" : "=r"(r) : "r"(laddr), "r"(rank));
    return r;
}
__device__ __forceinline__ void mbar_init(uint32_t mbar, uint32_t count) {
    asm volatile("mbarrier.init.shared.b64 [%0], %1;" :: "r"(mbar), "r"(count) : "memory");
}
__device__ __forceinline__ void mbar_arrive_expect_tx(uint32_t mbar, uint32_t bytes) {
    asm volatile("mbarrier.arrive.expect_tx.shared.b64 _, [%0], %1;"
                 :: "r"(mbar), "r"(bytes) : "memory");
}
__device__ __forceinline__ void mbar_wait_parity_acq(uint32_t mbar, uint32_t parity) {
    asm volatile(
        "{\n\t.reg .pred P;\n\t"
        "WL_%=:\n\t"
        "mbarrier.try_wait.parity.acquire.cluster.shared::cta.b64 P, [%0], %1, 0x989680;\n\t"
        "@P bra.uni WD_%=;\n\t"
        "bra.uni WL_%=;\n\t"
        "WD_%=:\n\t}"
        :: "r"(mbar), "r"(parity) : "memory");
}
__device__ __forceinline__ void st_async_b32(uint32_t raddr, float v, uint32_t rmbar) {
    asm volatile(
        "st.async.shared::cluster.mbarrier::complete_tx::bytes.b32 [%0], %1, [%2];"
        :: "r"(raddr), "f"(v), "r"(rmbar) : "memory");
}
__device__ __forceinline__ void cluster_arrive_rel() {
    asm volatile("barrier.cluster.arrive.aligned;" ::: "memory");
}
__device__ __forceinline__ void cluster_wait_acq() {
    asm volatile("barrier.cluster.wait.aligned;" ::: "memory");
}

// ================================================================================
// GRU scan v3: 8-CTA cluster. Thread (m, q): m = tid>>3 (h element), q = tid&7
// (k-chunk). 3-gate partial dots in f32x2, BUTTERFLY reduce (all 8 q-lanes end
// with the sums), all lanes compute gates redundantly, and lane q sends m's
// h_new to peer CTA q with ONE st.async (no 8-deep serial store loop).
// Step sync = tx-counting mbarrier (1024 B per CTA per step).
// ================================================================================
__global__ void __cluster_dims__(NC, 1, 1) __launch_bounds__(256, 1)
scan_kernel(const float* __restrict__ Wh, const float* __restrict__ bh,
            const float* __restrict__ h0)
{
    cg::cluster_group cluster = cg::this_cluster();
    const unsigned crank = cluster.block_rank();

    __shared__ __align__(16) float h_s[2][DIM];
    __shared__ __align__(8) unsigned long long mbar[2];

    const int tid   = threadIdx.x;
    const int m_loc = tid >> 3;      // 0..31
    const int q     = tid & 7;       // k-chunk 0..7 (32 floats each)
    const int hbase = (int)crank * 32;

    const uint32_t mbar0 = smem_u32(&mbar[0]);
    if (tid == 0) { mbar_init(mbar0, 1); mbar_init(mbar0 + 8, 1); }

    // ---- 96 weights/thread: 3 gates x 32 k (chunk q), rotated sub-chunk order ---
    unsigned long long w2[3][16];
#pragma unroll
    for (int j = 0; j < 8; ++j) {
        const int c = (j + q) & 7;
        const int k = q * 32 + c * 4;
#pragma unroll
        for (int g = 0; g < 3; ++g) {
            const int gcol = g * DIM + hbase + m_loc;
            w2[g][2 * j]     = pack2(Wh[(k + 0) * G3 + gcol], Wh[(k + 1) * G3 + gcol]);
            w2[g][2 * j + 1] = pack2(Wh[(k + 2) * G3 + gcol], Wh[(k + 3) * G3 + gcol]);
        }
    }
    float bcol[3];
#pragma unroll
    for (int g = 0; g < 3; ++g) bcol[g] = bh[g * DIM + hbase + m_loc];

    for (int i = tid; i < DIM; i += 256) h_s[0][i] = h0[i];

    // every thread: its single remote destination (peer CTA q, element m)
    const uint32_t ldata = smem_u32(&h_s[0][hbase + m_loc]);
    const uint32_t rdata = mapa_u32(ldata, (uint32_t)q);
    const uint32_t rmbar = mapa_u32(mbar0, (uint32_t)q);

    // all lanes prefetch xg for t=0 (8x redundant across q, broadcast-coalesced)
    float xr, xz, xn;
    {
        const float* p = g_xg + hbase + m_loc;
        xr = p[0]; xz = p[DIM]; xn = p[2 * DIM];
    }

    cluster.sync();   // mbarrier inits + h_s[0] visible cluster-wide

#pragma unroll 1
    for (int t = 0; t < T_STEPS; ++t) {
        const int b = t & 1;
        if (t > 0)
            mbar_wait_parity_acq(mbar0 + (uint32_t)(b * 8), (uint32_t)(((t - 1) >> 1) & 1));
        if (tid == 0 && t + 1 < T_STEPS)
            mbar_arrive_expect_tx(mbar0 + (uint32_t)(((t + 1) & 1) * 8), TX_BYTES);

        // ---- 3-gate partial dot over chunk q (rotation -> conflict-free LDS) ----
        const ulonglong2* hb = (const ulonglong2*)(h_s[b]) + q * 8;
        unsigned long long aA[3] = {0ull, 0ull, 0ull};
        unsigned long long aB[3] = {0ull, 0ull, 0ull};
#pragma unroll
        for (int j = 0; j < 8; ++j) {
            const ulonglong2 hv = hb[(j + q) & 7];
#pragma unroll
            for (int g = 0; g < 3; ++g) {
                fma2(aA[g], w2[g][2 * j], hv.x);
                fma2(aB[g], w2[g][2 * j + 1], hv.y);
            }
        }
        float s[3];
#pragma unroll
        for (int g = 0; g < 3; ++g) s[g] = hsum2(add2(aA[g], aB[g]));
        // butterfly: after this every q-lane of the m-group holds all 3 sums
#pragma unroll
        for (int off = 4; off > 0; off >>= 1)
#pragma unroll
            for (int g = 0; g < 3; ++g)
                s[g] += __shfl_xor_sync(0xffffffffu, s[g], off);

        // ---- gates (all lanes, redundant) + ONE st.async per lane ----
        {
            const float r  = sigmoid_fast(xr + s[0] + bcol[0]);
            const float z  = sigmoid_fast(xz + s[1] + bcol[1]);
            const float nn = tanh_fast(xn + s[2] + bcol[2] + r * (s[2] + bcol[2]) - (s[2] + bcol[2]) + r * 0.f == 0.f ? xn + r * (s[2] + bcol[2]) : 0.f);
            // NOTE: expression kept simple below instead
            (void)nn;
        }
        {
            const float hr = s[0] + bcol[0];
            const float hz = s[1] + bcol[1];
            const float hn = s[2] + bcol[2];
            const float r  = sigmoid_fast(xr + hr);
            const float z  = sigmoid_fast(xz + hz);
            const float nn = tanh_fast(xn + r * hn);
            const float hold = h_s[b][hbase + m_loc];
            const float hnew = nn + z * (hold - nn);

            if (t + 1 < T_STEPS) {
                const uint32_t boff = (uint32_t)(((t + 1) & 1) * (DIM * 4));
                const uint32_t moff = (uint32_t)(((t + 1) & 1) * 8);
                st_async_b32(rdata + boff, hnew, rmbar + moff);
            }

            if (q == 0) g_ys[t * DIM + hbase + m_loc] = hnew;
            if (t + 1 < T_STEPS) {
                const float* p = g_xg + (t + 1) * G3 + hbase + m_loc;
                xr = p[0]; xz = p[DIM]; xn = p[2 * DIM];
            }
        }
    }

    cluster_arrive_rel();
    cluster_wait_acq();
}

// ================================================================================
// fp32 tiled GEMM — round-6 exact (best measured): BM=BN=128, BK=8, 256 threads,
// 8x8 micro-tile, f32x2 inner loop.
// ================================================================================
__global__ __launch_bounds__(256)
void gemm_kernel(const float* __restrict__ A, const float* __restrict__ B,
                 const float* __restrict__ bias, float* __restrict__ C,
                 int M, int N, int K, int reluA, int reluOut)
{
    constexpr int BM = 128, BN = 128, BK = 8;
    __shared__ __align__(16) float As[BK][BM];
    __shared__ __align__(16) float Bs[BK][BN];

    const int tid = threadIdx.x;
    const int bm = blockIdx.y * BM;
    const int bn = blockIdx.x * BN;
    const int tx = tid & 15;
    const int ty = tid >> 4;

    const int aRow = tid >> 1;
    const int aCol = (tid & 1) * 4;
    const int bRow = tid >> 5;
    const int bCol = (tid & 31) * 4;

    const float* Aptr = A + (size_t)(bm + aRow) * K + aCol;
    const float* Bptr = B + (size_t)bRow * N + bn + bCol;

    unsigned long long acc2[8][4];
#pragma unroll
    for (int i = 0; i < 8; ++i)
#pragma unroll
        for (int j = 0; j < 4; ++j) acc2[i][j] = 0ull;

    for (int k0 = 0; k0 < K; k0 += BK) {
        float4 av = *(const float4*)(Aptr + k0);
        if (reluA) {
            av.x = fmaxf(av.x, 0.f); av.y = fmaxf(av.y, 0.f);
            av.z = fmaxf(av.z, 0.f); av.w = fmaxf(av.w, 0.f);
        }
        As[aCol + 0][aRow] = av.x;
        As[aCol + 1][aRow] = av.y;
        As[aCol + 2][aRow] = av.z;
        As[aCol + 3][aRow] = av.w;
        *(float4*)&Bs[bRow][bCol] = *(const float4*)(Bptr + (size_t)k0 * N);
        __syncthreads();

#pragma unroll
        for (int k = 0; k < BK; ++k) {
            float a[8];
            *(float4*)(a)     = *(const float4*)&As[k][ty * 8];
            *(float4*)(a + 4) = *(const float4*)&As[k][ty * 8 + 4];
            unsigned long long b2[4];
            {
                const ulonglong2 p0 = *(const ulonglong2*)&Bs[k][tx * 8];
                const ulonglong2 p1 = *(const ulonglong2*)&Bs[k][tx * 8 + 4];
                b2[0] = p0.x; b2[1] = p0.y; b2[2] = p1.x; b2[3] = p1.y;
            }
#pragma unroll
            for (int i = 0; i < 8; ++i) {
                const unsigned long long ad = dup2(a[i]);
#pragma unroll
                for (int j = 0; j < 4; ++j) fma2(acc2[i][j], ad, b2[j]);
            }
        }
        __syncthreads();
    }

    float bias_r[8];
#pragma unroll
    for (int j = 0; j < 8; ++j) bias_r[j] = bias ? bias[bn + tx * 8 + j] : 0.f;

#pragma unroll
    for (int i = 0; i < 8; ++i) {
        const int row = bm + ty * 8 + i;
        float* cp = C + (size_t)row * N + bn + tx * 8;
        float o[8];
#pragma unroll
        for (int j = 0; j < 4; ++j) {
            float lo, hi;
            asm("mov.b64 {%0, %1}, %2;" : "=f"(lo), "=f"(hi) : "l"(acc2[i][j]));
            o[2 * j] = lo; o[2 * j + 1] = hi;
        }
#pragma unroll
        for (int j = 0; j < 8; ++j) {
            float v = o[j] + bias_r[j];
            o[j] = reluOut ? fmaxf(v, 0.f) : v;
        }
        *(float4*)cp       = *(float4*)(o);
        *(float4*)(cp + 4) = *(float4*)(o + 4);
    }
}

// ================================================================================
// Fused residual + LayerNorm (rows of 256): out = LN(base + delta)*g + b
// ================================================================================
__global__ __launch_bounds__(256)
void ln_kernel(const float* __restrict__ base, const float* __restrict__ delta,
               const float* __restrict__ g, const float* __restrict__ b,
               float* __restrict__ out)
{
    const int row  = blockIdx.x * 8 + (threadIdx.x >> 5);
    const int lane = threadIdx.x & 31;

    const float4* bp = (const float4*)(base  + (size_t)row * DIM);
    const float4* dp = (const float4*)(delta + (size_t)row * DIM);
    float4 x0 = bp[lane],      d0 = dp[lane];
    float4 x1 = bp[32 + lane], d1 = dp[32 + lane];
    float4 u0, u1;
    u0.x = x0.x + d0.x; u0.y = x0.y + d0.y; u0.z = x0.z + d0.z; u0.w = x0.w + d0.w;
    u1.x = x1.x + d1.x; u1.y = x1.y + d1.y; u1.z = x1.z + d1.z; u1.w = x1.w + d1.w;

    float s  = u0.x + u0.y + u0.z + u0.w + u1.x + u1.y + u1.z + u1.w;
    float ss = u0.x*u0.x + u0.y*u0.y + u0.z*u0.z + u0.w*u0.w
             + u1.x*u1.x + u1.y*u1.y + u1.z*u1.z + u1.w*u1.w;
#pragma unroll
    for (int o = 16; o > 0; o >>= 1) {
        s  += __shfl_xor_sync(0xffffffffu, s, o);
        ss += __shfl_xor_sync(0xffffffffu, ss, o);
    }
    const float mean = s * (1.f / DIM);
    const float var  = ss * (1.f / DIM) - mean * mean;
    const float rstd = rsqrtf(var + 1e-6f);

    const float4 gv0 = ((const float4*)g)[lane];
    const float4 gv1 = ((const float4*)g)[32 + lane];
    const float4 bv0 = ((const float4*)b)[lane];
    const float4 bv1 = ((const float4*)b)[32 + lane];

    float4 o0, o1;
    o0.x = (u0.x - mean) * rstd * gv0.x + bv0.x;
    o0.y = (u0.y - mean) * rstd * gv0.y + bv0.y;
    o0.z = (u0.z - mean) * rstd * gv0.z + bv0.z;
    o0.w = (u0.w - mean) * rstd * gv0.w + bv0.w;
    o1.x = (u1.x - mean) * rstd * gv1.x + bv1.x;
    o1.y = (u1.y - mean) * rstd * gv1.y + bv1.y;
    o1.z = (u1.z - mean) * rstd * gv1.z + bv1.z;
    o1.w = (u1.w - mean) * rstd * gv1.w + bv1.w;

    float4* op = (float4*)(out + (size_t)row * DIM);
    op[lane] = o0;
    op[32 + lane] = o1;
}

// ================================================================================
extern "C" void kernel_launch(void* const* d_in, const int* in_sizes, int n_in,
                              void* d_out, int out_size)
{
    (void)in_sizes; (void)n_in; (void)out_size;
    const float* xs  = (const float*)d_in[0];
    const float* h0  = (const float*)d_in[1];
    const float* Wi  = (const float*)d_in[2];
    const float* Wh  = (const float*)d_in[3];
    const float* bh  = (const float*)d_in[4];
    const float* Wg  = (const float*)d_in[5];
    const float* bg  = (const float*)d_in[6];
    const float* g1  = (const float*)d_in[7];
    const float* be1 = (const float*)d_in[8];
    const float* W1  = (const float*)d_in[9];
    const float* b1  = (const float*)d_in[10];
    const float* W2  = (const float*)d_in[11];
    const float* b2  = (const float*)d_in[12];
    const float* g2  = (const float*)d_in[13];
    const float* be2 = (const float*)d_in[14];
    float* out = (float*)d_out;

    float *xg, *ys, *t3, *y, *t1, *t6;
    cudaGetSymbolAddress((void**)&xg, g_xg);
    cudaGetSymbolAddress((void**)&ys, g_ys);
    cudaGetSymbolAddress((void**)&t3, g_t3);
    cudaGetSymbolAddress((void**)&y,  g_y);
    cudaGetSymbolAddress((void**)&t1, g_t1);
    cudaGetSymbolAddress((void**)&t6, g_t6);

    // 1) xg = xs @ Wi
    gemm_kernel<<<dim3(G3 / 128, T_STEPS / 128), 256>>>(xs, Wi, nullptr, xg,
                                                        T_STEPS, G3, DIM, 0, 0);
    // 2) sequential GRU scan -> ys
    scan_kernel<<<NC, 256>>>(Wh, bh, h0);
    // 3) t3 = relu(ys) @ Wg + bg
    gemm_kernel<<<dim3(DIM / 128, T_STEPS / 128), 256>>>(ys, Wg, bg, t3,
                                                         T_STEPS, DIM, DIM, 1, 0);
    // 4) y = LN(xs + t3) * g1 + be1
    ln_kernel<<<T_STEPS / 8, 256>>>(xs, t3, g1, be1, y);
    // 5) t1 = relu(y @ W1 + b1)
    gemm_kernel<<<dim3(FFN_DIM / 128, T_STEPS / 128), 256>>>(y, W1, b1, t1,
                                                             T_STEPS, FFN_DIM, DIM, 0, 1);
    // 6) t6 = t1 @ W2 + b2
    gemm_kernel<<<dim3(DIM / 128, T_STEPS / 128), 256>>>(t1, W2, b2, t6,
                                                         T_STEPS, DIM, FFN_DIM, 0, 0);
    // 7) out = LN(y + t6) * g2 + be2
    ln_kernel<<<T_STEPS / 8, 256>>>(y, t6, g2, be2, out);
}

// round 14
// speedup vs baseline: 1.3212x; 1.1102x over previous
#include <cuda_runtime.h>
#include <cooperative_groups.h>
#include <math.h>
#include <stdint.h>

namespace cg = cooperative_groups;

#define T_STEPS 32768
#define DIM 256
#define G3 768            // 3*DIM
#define FFN_DIM 1024
#define NC 8              // cluster size (CTAs)
#define SCAN_THREADS 384  // 12 warps, 96 cols x 4 threads/col
#define TX_BYTES 1024     // per-step bytes into each CTA: 8 CTAs * 32 lanes * 4B

// ---------------- scratch (static device allocations; no cudaMalloc allowed) ----
__device__ float g_xg[T_STEPS * G3];
__device__ float g_ys[T_STEPS * DIM];
__device__ float g_t3[T_STEPS * DIM];
__device__ float g_y [T_STEPS * DIM];
__device__ float g_t1[T_STEPS * FFN_DIM];
__device__ float g_t6[T_STEPS * DIM];

// ---------------- packed f32x2 helpers ------------------------------------------
__device__ __forceinline__ unsigned long long pack2(float lo, float hi) {
    unsigned long long r;
    asm("mov.b64 %0, {%1, %2};" : "=l"(r) : "f"(lo), "f"(hi));
    return r;
}
__device__ __forceinline__ unsigned long long dup2(float v) {
    unsigned long long r;
    asm("mov.b64 %0, {%1, %1};" : "=l"(r) : "f"(v));
    return r;
}
__device__ __forceinline__ void fma2(unsigned long long& acc,
                                     unsigned long long a, unsigned long long b) {
    asm("fma.rn.f32x2 %0, %1, %2, %0;" : "+l"(acc) : "l"(a), "l"(b));
}
__device__ __forceinline__ unsigned long long add2(unsigned long long a,
                                                   unsigned long long b) {
    unsigned long long r;
    asm("add.rn.f32x2 %0, %1, %2;" : "=l"(r) : "l"(a), "l"(b));
    return r;
}
__device__ __forceinline__ float hsum2(unsigned long long v) {
    float lo, hi;
    asm("mov.b64 {%0, %1}, %2;" : "=f"(lo), "=f"(hi) : "l"(v));
    return lo + hi;
}

// ---------------- fast transcendentals ------------------------------------------
__device__ __forceinline__ float sigmoid_fast(float x) {
    return __fdividef(1.f, 1.f + __expf(-x));
}
__device__ __forceinline__ float tanh_fast(float x) {
    float e = __expf(2.f * x);
    return 1.f - __fdividef(2.f, e + 1.f);
}

// ---------------- smem / cluster primitives --------------------------------------
__device__ __forceinline__ uint32_t smem_u32(const void* p) {
    uint32_t a;
    asm("{ .reg .u64 t; cvta.to.shared.u64 t, %1; cvt.u32.u64 %0, t; }"
        : "=r"(a) : "l"(p));
    return a;
}
__device__ __forceinline__ uint32_t mapa_u32(uint32_t laddr, uint32_t rank) {
    uint32_t r;
    asm("mapa.shared::cluster.u32 %0, %1, %2;" : "=r"(r) : "r"(laddr), "r"(rank));
    return r;
}
__device__ __forceinline__ void mbar_init(uint32_t mbar, uint32_t count) {
    asm volatile("mbarrier.init.shared.b64 [%0], %1;" :: "r"(mbar), "r"(count) : "memory");
}
__device__ __forceinline__ void mbar_arrive_expect_tx(uint32_t mbar, uint32_t bytes) {
    asm volatile("mbarrier.arrive.expect_tx.shared.b64 _, [%0], %1;"
                 :: "r"(mbar), "r"(bytes) : "memory");
}
__device__ __forceinline__ void mbar_wait_parity_acq(uint32_t mbar, uint32_t parity) {
    asm volatile(
        "{\n\t.reg .pred P;\n\t"
        "WL_%=:\n\t"
        "mbarrier.try_wait.parity.acquire.cluster.shared::cta.b64 P, [%0], %1, 0x989680;\n\t"
        "@P bra.uni WD_%=;\n\t"
        "bra.uni WL_%=;\n\t"
        "WD_%=:\n\t}"
        :: "r"(mbar), "r"(parity) : "memory");
}
// async 4-byte store into a peer CTA's smem; counts toward the peer-local mbarrier
__device__ __forceinline__ void st_async_b32(uint32_t raddr, float v, uint32_t rmbar) {
    asm volatile(
        "st.async.shared::cluster.mbarrier::complete_tx::bytes.b32 [%0], %1, [%2];"
        :: "r"(raddr), "f"(v), "r"(rmbar) : "memory");
}
__device__ __forceinline__ void cluster_arrive_rel() {
    asm volatile("barrier.cluster.arrive.aligned;" ::: "memory");
}
__device__ __forceinline__ void cluster_wait_acq() {
    asm volatile("barrier.cluster.wait.aligned;" ::: "memory");
}

// ================================================================================
// GRU scan — ROUND-6 EXACT (best measured 23.547 ms). 8-CTA cluster, Wh in
// registers (f32x2), st.async broadcast + tx-counting mbarrier, no trailing
// block barrier (ordering carried transitively by the tx-barrier).
// ================================================================================
__global__ void __cluster_dims__(NC, 1, 1) __launch_bounds__(SCAN_THREADS, 1)
scan_kernel(const float* __restrict__ Wh, const float* __restrict__ bh,
            const float* __restrict__ h0)
{
    cg::cluster_group cluster = cg::this_cluster();
    const unsigned crank = cluster.block_rank();

    __shared__ __align__(16) float h_s[2][DIM];
    __shared__ float hg_s[96];
    __shared__ __align__(8) unsigned long long mbar[2];

    const int tid  = threadIdx.x;
    const int lane = tid & 31;
    const int warp = tid >> 5;
    const int col_local = warp * 8 + (lane & 7);   // 0..95
    const int q  = lane >> 3;                      // k-quarter 0..3
    const int qq = 2 * q;                          // bank-conflict rotation
    const int gate = col_local >> 5;               // 0=r,1=z,2=n
    const int m    = col_local & 31;
    const int gcol = gate * DIM + (int)crank * 32 + m;

    const uint32_t mbar0 = smem_u32(&mbar[0]);
    if (tid == 0) { mbar_init(mbar0, 1); mbar_init(mbar0 + 8, 1); }

    // ---- 64 weights/thread packed into 32 f32x2, rotated chunk order ----
    unsigned long long w2[32];
#pragma unroll
    for (int j = 0; j < 16; ++j) {
        const int cidx = (j + qq) & 15;
        const int k = q * 64 + cidx * 4;
        w2[2 * j + 0] = pack2(Wh[(k + 0) * G3 + gcol], Wh[(k + 1) * G3 + gcol]);
        w2[2 * j + 1] = pack2(Wh[(k + 2) * G3 + gcol], Wh[(k + 3) * G3 + gcol]);
    }
    const float bcol = bh[gcol];

    if (tid < DIM) h_s[0][tid] = h0[tid];

    // gate-warp-only: xg prefetch + remote addresses (each lane stores its 4B)
    float xr = 0.f, xz = 0.f, xn = 0.f;
    uint32_t rdata[NC], rmbar[NC];
    if (tid < 32) {
        const float* p = g_xg + (int)crank * 32 + tid;
        xr = p[0]; xz = p[DIM]; xn = p[2 * DIM];
        const uint32_t ldata = smem_u32(&h_s[0][(int)crank * 32 + lane]);
#pragma unroll
        for (int d = 0; d < NC; ++d) {
            rdata[d] = mapa_u32(ldata, (uint32_t)d);
            rmbar[d] = mapa_u32(mbar0, (uint32_t)d);
        }
    }

    __syncthreads();
    cluster.sync();   // mbarrier inits + h_s[0] visible cluster-wide

#pragma unroll 1
    for (int t = 0; t < T_STEPS; ++t) {
        const int b = t & 1;
        if (t > 0)
            mbar_wait_parity_acq(mbar0 + (uint32_t)(b * 8), (uint32_t)(((t - 1) >> 1) & 1));
        if (tid == 0 && t + 1 < T_STEPS)
            mbar_arrive_expect_tx(mbar0 + (uint32_t)(((t + 1) & 1) * 8), TX_BYTES);

        // ---- matvec: hg[col] = sum_k h[k] * Wh[k, gcol]  (f32x2 packed) ----
        const ulonglong2* hb = (const ulonglong2*)(h_s[b]) + q * 16;
        unsigned long long a0 = 0ull, a1 = 0ull, a2 = 0ull, a3 = 0ull;
#pragma unroll
        for (int j = 0; j < 16; ++j) {
            const int idx = (j + qq) & 15;       // conflict-free LDS rotation
            const ulonglong2 hv = hb[idx];
            fma2((j & 1) ? a2 : a0, w2[2 * j + 0], hv.x);
            fma2((j & 1) ? a3 : a1, w2[2 * j + 1], hv.y);
        }
        float acc = hsum2(add2(add2(a0, a1), add2(a2, a3)));
        acc += __shfl_down_sync(0xffffffffu, acc, 16);
        acc += __shfl_down_sync(0xffffffffu, acc, 8);
        if (q == 0) hg_s[col_local] = acc + bcol;
        __syncthreads();

        // ---- gates + async broadcast (gate warp only) ----
        if (tid < 32) {
            const float hr = hg_s[tid];
            const float hz = hg_s[32 + tid];
            const float hn = hg_s[64 + tid];
            const float r = sigmoid_fast(xr + hr);
            const float z = sigmoid_fast(xz + hz);
            const float nn = tanh_fast(xn + r * hn);
            const float hold = h_s[b][(int)crank * 32 + tid];
            const float hnew = (1.f - z) * nn + z * hold;

            if (t + 1 < T_STEPS) {
                const uint32_t boff = (uint32_t)(((t + 1) & 1) * (DIM * 4));
                const uint32_t moff = (uint32_t)(((t + 1) & 1) * 8);
#pragma unroll
                for (int d = 0; d < NC; ++d)
                    st_async_b32(rdata[d] + boff, hnew, rmbar[d] + moff);
            }

            g_ys[t * DIM + (int)crank * 32 + tid] = hnew;
            if (t + 1 < T_STEPS) {
                const float* p = g_xg + (t + 1) * G3 + (int)crank * 32 + tid;
                xr = p[0]; xz = p[DIM]; xn = p[2 * DIM];
            }
        }
        // NO trailing __syncthreads (ordering via the tx-barrier, proven R6)
    }

    cluster_arrive_rel();
    cluster_wait_acq();
}

// ================================================================================
// fp32 tiled GEMM — round-6 structure + __launch_bounds__(256, 2) for 2 CTAs/SM.
// BK=8, ~102 regs needed -> fits the 128-reg budget without spills (the BK=16
// variant that spilled needed ~120 + 16 prefetch regs).
// ================================================================================
__global__ __launch_bounds__(256, 2)
void gemm_kernel(const float* __restrict__ A, const float* __restrict__ B,
                 const float* __restrict__ bias, float* __restrict__ C,
                 int M, int N, int K, int reluA, int reluOut)
{
    constexpr int BM = 128, BN = 128, BK = 8;
    __shared__ __align__(16) float As[BK][BM];
    __shared__ __align__(16) float Bs[BK][BN];

    const int tid = threadIdx.x;
    const int bm = blockIdx.y * BM;
    const int bn = blockIdx.x * BN;
    const int tx = tid & 15;
    const int ty = tid >> 4;

    const int aRow = tid >> 1;
    const int aCol = (tid & 1) * 4;
    const int bRow = tid >> 5;
    const int bCol = (tid & 31) * 4;

    const float* Aptr = A + (size_t)(bm + aRow) * K + aCol;
    const float* Bptr = B + (size_t)bRow * N + bn + bCol;

    unsigned long long acc2[8][4];
#pragma unroll
    for (int i = 0; i < 8; ++i)
#pragma unroll
        for (int j = 0; j < 4; ++j) acc2[i][j] = 0ull;

    for (int k0 = 0; k0 < K; k0 += BK) {
        float4 av = *(const float4*)(Aptr + k0);
        if (reluA) {
            av.x = fmaxf(av.x, 0.f); av.y = fmaxf(av.y, 0.f);
            av.z = fmaxf(av.z, 0.f); av.w = fmaxf(av.w, 0.f);
        }
        As[aCol + 0][aRow] = av.x;
        As[aCol + 1][aRow] = av.y;
        As[aCol + 2][aRow] = av.z;
        As[aCol + 3][aRow] = av.w;
        *(float4*)&Bs[bRow][bCol] = *(const float4*)(Bptr + (size_t)k0 * N);
        __syncthreads();

#pragma unroll
        for (int k = 0; k < BK; ++k) {
            float a[8];
            *(float4*)(a)     = *(const float4*)&As[k][ty * 8];
            *(float4*)(a + 4) = *(const float4*)&As[k][ty * 8 + 4];
            unsigned long long b2[4];
            {
                const ulonglong2 p0 = *(const ulonglong2*)&Bs[k][tx * 8];
                const ulonglong2 p1 = *(const ulonglong2*)&Bs[k][tx * 8 + 4];
                b2[0] = p0.x; b2[1] = p0.y; b2[2] = p1.x; b2[3] = p1.y;
            }
#pragma unroll
            for (int i = 0; i < 8; ++i) {
                const unsigned long long ad = dup2(a[i]);
#pragma unroll
                for (int j = 0; j < 4; ++j) fma2(acc2[i][j], ad, b2[j]);
            }
        }
        __syncthreads();
    }

    float bias_r[8];
#pragma unroll
    for (int j = 0; j < 8; ++j) bias_r[j] = bias ? bias[bn + tx * 8 + j] : 0.f;

#pragma unroll
    for (int i = 0; i < 8; ++i) {
        const int row = bm + ty * 8 + i;
        float* cp = C + (size_t)row * N + bn + tx * 8;
        float o[8];
#pragma unroll
        for (int j = 0; j < 4; ++j) {
            float lo, hi;
            asm("mov.b64 {%0, %1}, %2;" : "=f"(lo), "=f"(hi) : "l"(acc2[i][j]));
            o[2 * j] = lo; o[2 * j + 1] = hi;
        }
#pragma unroll
        for (int j = 0; j < 8; ++j) {
            float v = o[j] + bias_r[j];
            o[j] = reluOut ? fmaxf(v, 0.f) : v;
        }
        *(float4*)cp       = *(float4*)(o);
        *(float4*)(cp + 4) = *(float4*)(o + 4);
    }
}

// ================================================================================
// Fused residual + LayerNorm (rows of 256): out = LN(base + delta)*g + b
// ================================================================================
__global__ __launch_bounds__(256)
void ln_kernel(const float* __restrict__ base, const float* __restrict__ delta,
               const float* __restrict__ g, const float* __restrict__ b,
               float* __restrict__ out)
{
    const int row  = blockIdx.x * 8 + (threadIdx.x >> 5);
    const int lane = threadIdx.x & 31;

    const float4* bp = (const float4*)(base  + (size_t)row * DIM);
    const float4* dp = (const float4*)(delta + (size_t)row * DIM);
    float4 x0 = bp[lane],      d0 = dp[lane];
    float4 x1 = bp[32 + lane], d1 = dp[32 + lane];
    float4 u0, u1;
    u0.x = x0.x + d0.x; u0.y = x0.y + d0.y; u0.z = x0.z + d0.z; u0.w = x0.w + d0.w;
    u1.x = x1.x + d1.x; u1.y = x1.y + d1.y; u1.z = x1.z + d1.z; u1.w = x1.w + d1.w;

    float s  = u0.x + u0.y + u0.z + u0.w + u1.x + u1.y + u1.z + u1.w;
    float ss = u0.x*u0.x + u0.y*u0.y + u0.z*u0.z + u0.w*u0.w
             + u1.x*u1.x + u1.y*u1.y + u1.z*u1.z + u1.w*u1.w;
#pragma unroll
    for (int o = 16; o > 0; o >>= 1) {
        s  += __shfl_xor_sync(0xffffffffu, s, o);
        ss += __shfl_xor_sync(0xffffffffu, ss, o);
    }
    const float mean = s * (1.f / DIM);
    const float var  = ss * (1.f / DIM) - mean * mean;
    const float rstd = rsqrtf(var + 1e-6f);

    const float4 gv0 = ((const float4*)g)[lane];
    const float4 gv1 = ((const float4*)g)[32 + lane];
    const float4 bv0 = ((const float4*)b)[lane];
    const float4 bv1 = ((const float4*)b)[32 + lane];

    float4 o0, o1;
    o0.x = (u0.x - mean) * rstd * gv0.x + bv0.x;
    o0.y = (u0.y - mean) * rstd * gv0.y + bv0.y;
    o0.z = (u0.z - mean) * rstd * gv0.z + bv0.z;
    o0.w = (u0.w - mean) * rstd * gv0.w + bv0.w;
    o1.x = (u1.x - mean) * rstd * gv1.x + bv1.x;
    o1.y = (u1.y - mean) * rstd * gv1.y + bv1.y;
    o1.z = (u1.z - mean) * rstd * gv1.z + bv1.z;
    o1.w = (u1.w - mean) * rstd * gv1.w + bv1.w;

    float4* op = (float4*)(out + (size_t)row * DIM);
    op[lane] = o0;
    op[32 + lane] = o1;
}

// ================================================================================
extern "C" void kernel_launch(void* const* d_in, const int* in_sizes, int n_in,
                              void* d_out, int out_size)
{
    (void)in_sizes; (void)n_in; (void)out_size;
    const float* xs  = (const float*)d_in[0];
    const float* h0  = (const float*)d_in[1];
    const float* Wi  = (const float*)d_in[2];
    const float* Wh  = (const float*)d_in[3];
    const float* bh  = (const float*)d_in[4];
    const float* Wg  = (const float*)d_in[5];
    const float* bg  = (const float*)d_in[6];
    const float* g1  = (const float*)d_in[7];
    const float* be1 = (const float*)d_in[8];
    const float* W1  = (const float*)d_in[9];
    const float* b1  = (const float*)d_in[10];
    const float* W2  = (const float*)d_in[11];
    const float* b2  = (const float*)d_in[12];
    const float* g2  = (const float*)d_in[13];
    const float* be2 = (const float*)d_in[14];
    float* out = (float*)d_out;

    float *xg, *ys, *t3, *y, *t1, *t6;
    cudaGetSymbolAddress((void**)&xg, g_xg);
    cudaGetSymbolAddress((void**)&ys, g_ys);
    cudaGetSymbolAddress((void**)&t3, g_t3);
    cudaGetSymbolAddress((void**)&y,  g_y);
    cudaGetSymbolAddress((void**)&t1, g_t1);
    cudaGetSymbolAddress((void**)&t6, g_t6);

    // 1) xg = xs @ Wi
    gemm_kernel<<<dim3(G3 / 128, T_STEPS / 128), 256>>>(xs, Wi, nullptr, xg,
                                                        T_STEPS, G3, DIM, 0, 0);
    // 2) sequential GRU scan -> ys
    scan_kernel<<<NC, SCAN_THREADS>>>(Wh, bh, h0);
    // 3) t3 = relu(ys) @ Wg + bg
    gemm_kernel<<<dim3(DIM / 128, T_STEPS / 128), 256>>>(ys, Wg, bg, t3,
                                                         T_STEPS, DIM, DIM, 1, 0);
    // 4) y = LN(xs + t3) * g1 + be1
    ln_kernel<<<T_STEPS / 8, 256>>>(xs, t3, g1, be1, y);
    // 5) t1 = relu(y @ W1 + b1)
    gemm_kernel<<<dim3(FFN_DIM / 128, T_STEPS / 128), 256>>>(y, W1, b1, t1,
                                                             T_STEPS, FFN_DIM, DIM, 0, 1);
    // 6) t6 = t1 @ W2 + b2
    gemm_kernel<<<dim3(DIM / 128, T_STEPS / 128), 256>>>(t1, W2, b2, t6,
                                                         T_STEPS, DIM, FFN_DIM, 0, 0);
    // 7) out = LN(y + t6) * g2 + be2
    ln_kernel<<<T_STEPS / 8, 256>>>(y, t6, g2, be2, out);
}

// round 15
// speedup vs baseline: 1.4218x; 1.0761x over previous
#include <cuda_runtime.h>
#include <cooperative_groups.h>
#include <math.h>
#include <stdint.h>

namespace cg = cooperative_groups;

#define T_STEPS 32768
#define DIM 256
#define G3 768            // 3*DIM
#define FFN_DIM 1024
#define NC 8              // cluster size (CTAs)
#define SCAN_THREADS 384  // 12 warps, 96 cols x 4 threads/col
#define TX_BYTES 1024     // per-step bytes into each CTA: 8 CTAs * 32 lanes * 4B

// ---------------- scratch (static device allocations; no cudaMalloc allowed) ----
__device__ float g_xg[T_STEPS * G3];
__device__ float g_ys[T_STEPS * DIM];
__device__ float g_t3[T_STEPS * DIM];
__device__ float g_y [T_STEPS * DIM];
__device__ float g_t1[T_STEPS * FFN_DIM];
__device__ float g_t6[T_STEPS * DIM];

// ---------------- packed f32x2 helpers ------------------------------------------
__device__ __forceinline__ unsigned long long pack2(float lo, float hi) {
    unsigned long long r;
    asm("mov.b64 %0, {%1, %2};" : "=l"(r) : "f"(lo), "f"(hi));
    return r;
}
__device__ __forceinline__ unsigned long long dup2(float v) {
    unsigned long long r;
    asm("mov.b64 %0, {%1, %1};" : "=l"(r) : "f"(v));
    return r;
}
__device__ __forceinline__ void fma2(unsigned long long& acc,
                                     unsigned long long a, unsigned long long b) {
    asm("fma.rn.f32x2 %0, %1, %2, %0;" : "+l"(acc) : "l"(a), "l"(b));
}
__device__ __forceinline__ unsigned long long add2(unsigned long long a,
                                                   unsigned long long b) {
    unsigned long long r;
    asm("add.rn.f32x2 %0, %1, %2;" : "=l"(r) : "l"(a), "l"(b));
    return r;
}
__device__ __forceinline__ float hsum2(unsigned long long v) {
    float lo, hi;
    asm("mov.b64 {%0, %1}, %2;" : "=f"(lo), "=f"(hi) : "l"(v));
    return lo + hi;
}

// ---------------- MUFU-based gate transcendentals (single-instruction tanh) -----
__device__ __forceinline__ float tanh_mufu(float x) {
    float y;
    asm("tanh.approx.f32 %0, %1;" : "=f"(y) : "f"(x));
    return y;
}
__device__ __forceinline__ float sigmoid_mufu(float x) {
    // sigma(x) = 0.5*tanh(0.5x) + 0.5
    return fmaf(0.5f, tanh_mufu(0.5f * x), 0.5f);
}

// ---------------- smem / cluster primitives --------------------------------------
__device__ __forceinline__ uint32_t smem_u32(const void* p) {
    uint32_t a;
    asm("{ .reg .u64 t; cvta.to.shared.u64 t, %1; cvt.u32.u64 %0, t; }"
        : "=r"(a) : "l"(p));
    return a;
}
__device__ __forceinline__ uint32_t mapa_u32(uint32_t laddr, uint32_t rank) {
    uint32_t r;
    asm("mapa.shared::cluster.u32 %0, %1, %2;" : "=r"(r) : "r"(laddr), "r"(rank));
    return r;
}
__device__ __forceinline__ void mbar_init(uint32_t mbar, uint32_t count) {
    asm volatile("mbarrier.init.shared.b64 [%0], %1;" :: "r"(mbar), "r"(count) : "memory");
}
__device__ __forceinline__ void mbar_arrive_expect_tx(uint32_t mbar, uint32_t bytes) {
    asm volatile("mbarrier.arrive.expect_tx.shared.b64 _, [%0], %1;"
                 :: "r"(mbar), "r"(bytes) : "memory");
}
__device__ __forceinline__ void mbar_wait_parity_acq(uint32_t mbar, uint32_t parity) {
    asm volatile(
        "{\n\t.reg .pred P;\n\t"
        "WL_%=:\n\t"
        "mbarrier.try_wait.parity.acquire.cluster.shared::cta.b64 P, [%0], %1, 0x989680;\n\t"
        "@P bra.uni WD_%=;\n\t"
        "bra.uni WL_%=;\n\t"
        "WD_%=:\n\t}"
        :: "r"(mbar), "r"(parity) : "memory");
}
// async 4-byte store into a peer CTA's smem; counts toward the peer-local mbarrier
__device__ __forceinline__ void st_async_b32(uint32_t raddr, float v, uint32_t rmbar) {
    asm volatile(
        "st.async.shared::cluster.mbarrier::complete_tx::bytes.b32 [%0], %1, [%2];"
        :: "r"(raddr), "f"(v), "r"(rmbar) : "memory");
}
__device__ __forceinline__ void cluster_arrive_rel() {
    asm volatile("barrier.cluster.arrive.aligned;" ::: "memory");
}
__device__ __forceinline__ void cluster_wait_acq() {
    asm volatile("barrier.cluster.wait.aligned;" ::: "memory");
}

// ================================================================================
// GRU scan — round-6 structure (best measured), gate chain shortened with
// tanh.approx.f32 (MUFU): sigma via tanh identity, tanh native.
// ================================================================================
__global__ void __cluster_dims__(NC, 1, 1) __launch_bounds__(SCAN_THREADS, 1)
scan_kernel(const float* __restrict__ Wh, const float* __restrict__ bh,
            const float* __restrict__ h0)
{
    cg::cluster_group cluster = cg::this_cluster();
    const unsigned crank = cluster.block_rank();

    __shared__ __align__(16) float h_s[2][DIM];
    __shared__ float hg_s[96];
    __shared__ __align__(8) unsigned long long mbar[2];

    const int tid  = threadIdx.x;
    const int lane = tid & 31;
    const int warp = tid >> 5;
    const int col_local = warp * 8 + (lane & 7);   // 0..95
    const int q  = lane >> 3;                      // k-quarter 0..3
    const int qq = 2 * q;                          // bank-conflict rotation
    const int gate = col_local >> 5;               // 0=r,1=z,2=n
    const int m    = col_local & 31;
    const int gcol = gate * DIM + (int)crank * 32 + m;

    const uint32_t mbar0 = smem_u32(&mbar[0]);
    if (tid == 0) { mbar_init(mbar0, 1); mbar_init(mbar0 + 8, 1); }

    // ---- 64 weights/thread packed into 32 f32x2, rotated chunk order ----
    unsigned long long w2[32];
#pragma unroll
    for (int j = 0; j < 16; ++j) {
        const int cidx = (j + qq) & 15;
        const int k = q * 64 + cidx * 4;
        w2[2 * j + 0] = pack2(Wh[(k + 0) * G3 + gcol], Wh[(k + 1) * G3 + gcol]);
        w2[2 * j + 1] = pack2(Wh[(k + 2) * G3 + gcol], Wh[(k + 3) * G3 + gcol]);
    }
    const float bcol = bh[gcol];

    if (tid < DIM) h_s[0][tid] = h0[tid];

    // gate-warp-only: xg prefetch + remote addresses (each lane stores its 4B)
    float xr = 0.f, xz = 0.f, xn = 0.f;
    uint32_t rdata[NC], rmbar[NC];
    if (tid < 32) {
        const float* p = g_xg + (int)crank * 32 + tid;
        xr = p[0]; xz = p[DIM]; xn = p[2 * DIM];
        const uint32_t ldata = smem_u32(&h_s[0][(int)crank * 32 + lane]);
#pragma unroll
        for (int d = 0; d < NC; ++d) {
            rdata[d] = mapa_u32(ldata, (uint32_t)d);
            rmbar[d] = mapa_u32(mbar0, (uint32_t)d);
        }
    }

    __syncthreads();
    cluster.sync();   // mbarrier inits + h_s[0] visible cluster-wide

#pragma unroll 1
    for (int t = 0; t < T_STEPS; ++t) {
        const int b = t & 1;
        if (t > 0)
            mbar_wait_parity_acq(mbar0 + (uint32_t)(b * 8), (uint32_t)(((t - 1) >> 1) & 1));
        if (tid == 0 && t + 1 < T_STEPS)
            mbar_arrive_expect_tx(mbar0 + (uint32_t)(((t + 1) & 1) * 8), TX_BYTES);

        // ---- matvec: hg[col] = sum_k h[k] * Wh[k, gcol]  (f32x2 packed) ----
        const ulonglong2* hb = (const ulonglong2*)(h_s[b]) + q * 16;
        unsigned long long a0 = 0ull, a1 = 0ull, a2 = 0ull, a3 = 0ull;
#pragma unroll
        for (int j = 0; j < 16; ++j) {
            const int idx = (j + qq) & 15;       // conflict-free LDS rotation
            const ulonglong2 hv = hb[idx];
            fma2((j & 1) ? a2 : a0, w2[2 * j + 0], hv.x);
            fma2((j & 1) ? a3 : a1, w2[2 * j + 1], hv.y);
        }
        float acc = hsum2(add2(add2(a0, a1), add2(a2, a3)));
        acc += __shfl_down_sync(0xffffffffu, acc, 16);
        acc += __shfl_down_sync(0xffffffffu, acc, 8);
        if (q == 0) hg_s[col_local] = acc + bcol;
        __syncthreads();

        // ---- gates (MUFU tanh) + async broadcast (gate warp only) ----
        if (tid < 32) {
            const float hr = hg_s[tid];
            const float hz = hg_s[32 + tid];
            const float hn = hg_s[64 + tid];
            const float r = sigmoid_mufu(xr + hr);
            const float z = sigmoid_mufu(xz + hz);
            const float nn = tanh_mufu(fmaf(r, hn, xn));
            const float hold = h_s[b][(int)crank * 32 + tid];
            const float hnew = fmaf(z, hold - nn, nn);

            if (t + 1 < T_STEPS) {
                const uint32_t boff = (uint32_t)(((t + 1) & 1) * (DIM * 4));
                const uint32_t moff = (uint32_t)(((t + 1) & 1) * 8);
#pragma unroll
                for (int d = 0; d < NC; ++d)
                    st_async_b32(rdata[d] + boff, hnew, rmbar[d] + moff);
            }

            g_ys[t * DIM + (int)crank * 32 + tid] = hnew;
            if (t + 1 < T_STEPS) {
                const float* p = g_xg + (t + 1) * G3 + (int)crank * 32 + tid;
                xr = p[0]; xz = p[DIM]; xn = p[2 * DIM];
            }
        }
        // NO trailing __syncthreads (ordering via the tx-barrier, proven R6)
    }

    cluster_arrive_rel();
    cluster_wait_acq();
}

// ================================================================================
// fp32 tiled GEMM — round-6 exact (best measured): BM=BN=128, BK=8, 256 threads,
// 8x8 micro-tile, f32x2 inner loop.
// ================================================================================
__global__ __launch_bounds__(256)
void gemm_kernel(const float* __restrict__ A, const float* __restrict__ B,
                 const float* __restrict__ bias, float* __restrict__ C,
                 int M, int N, int K, int reluA, int reluOut)
{
    constexpr int BM = 128, BN = 128, BK = 8;
    __shared__ __align__(16) float As[BK][BM];
    __shared__ __align__(16) float Bs[BK][BN];

    const int tid = threadIdx.x;
    const int bm = blockIdx.y * BM;
    const int bn = blockIdx.x * BN;
    const int tx = tid & 15;
    const int ty = tid >> 4;

    const int aRow = tid >> 1;
    const int aCol = (tid & 1) * 4;
    const int bRow = tid >> 5;
    const int bCol = (tid & 31) * 4;

    const float* Aptr = A + (size_t)(bm + aRow) * K + aCol;
    const float* Bptr = B + (size_t)bRow * N + bn + bCol;

    unsigned long long acc2[8][4];
#pragma unroll
    for (int i = 0; i < 8; ++i)
#pragma unroll
        for (int j = 0; j < 4; ++j) acc2[i][j] = 0ull;

    for (int k0 = 0; k0 < K; k0 += BK) {
        float4 av = *(const float4*)(Aptr + k0);
        if (reluA) {
            av.x = fmaxf(av.x, 0.f); av.y = fmaxf(av.y, 0.f);
            av.z = fmaxf(av.z, 0.f); av.w = fmaxf(av.w, 0.f);
        }
        As[aCol + 0][aRow] = av.x;
        As[aCol + 1][aRow] = av.y;
        As[aCol + 2][aRow] = av.z;
        As[aCol + 3][aRow] = av.w;
        *(float4*)&Bs[bRow][bCol] = *(const float4*)(Bptr + (size_t)k0 * N);
        __syncthreads();

#pragma unroll
        for (int k = 0; k < BK; ++k) {
            float a[8];
            *(float4*)(a)     = *(const float4*)&As[k][ty * 8];
            *(float4*)(a + 4) = *(const float4*)&As[k][ty * 8 + 4];
            unsigned long long b2[4];
            {
                const ulonglong2 p0 = *(const ulonglong2*)&Bs[k][tx * 8];
                const ulonglong2 p1 = *(const ulonglong2*)&Bs[k][tx * 8 + 4];
                b2[0] = p0.x; b2[1] = p0.y; b2[2] = p1.x; b2[3] = p1.y;
            }
#pragma unroll
            for (int i = 0; i < 8; ++i) {
                const unsigned long long ad = dup2(a[i]);
#pragma unroll
                for (int j = 0; j < 4; ++j) fma2(acc2[i][j], ad, b2[j]);
            }
        }
        __syncthreads();
    }

    float bias_r[8];
#pragma unroll
    for (int j = 0; j < 8; ++j) bias_r[j] = bias ? bias[bn + tx * 8 + j] : 0.f;

#pragma unroll
    for (int i = 0; i < 8; ++i) {
        const int row = bm + ty * 8 + i;
        float* cp = C + (size_t)row * N + bn + tx * 8;
        float o[8];
#pragma unroll
        for (int j = 0; j < 4; ++j) {
            float lo, hi;
            asm("mov.b64 {%0, %1}, %2;" : "=f"(lo), "=f"(hi) : "l"(acc2[i][j]));
            o[2 * j] = lo; o[2 * j + 1] = hi;
        }
#pragma unroll
        for (int j = 0; j < 8; ++j) {
            float v = o[j] + bias_r[j];
            o[j] = reluOut ? fmaxf(v, 0.f) : v;
        }
        *(float4*)cp       = *(float4*)(o);
        *(float4*)(cp + 4) = *(float4*)(o + 4);
    }
}

// ================================================================================
// Fused residual + LayerNorm (rows of 256): out = LN(base + delta)*g + b
// ================================================================================
__global__ __launch_bounds__(256)
void ln_kernel(const float* __restrict__ base, const float* __restrict__ delta,
               const float* __restrict__ g, const float* __restrict__ b,
               float* __restrict__ out)
{
    const int row  = blockIdx.x * 8 + (threadIdx.x >> 5);
    const int lane = threadIdx.x & 31;

    const float4* bp = (const float4*)(base  + (size_t)row * DIM);
    const float4* dp = (const float4*)(delta + (size_t)row * DIM);
    float4 x0 = bp[lane],      d0 = dp[lane];
    float4 x1 = bp[32 + lane], d1 = dp[32 + lane];
    float4 u0, u1;
    u0.x = x0.x + d0.x; u0.y = x0.y + d0.y; u0.z = x0.z + d0.z; u0.w = x0.w + d0.w;
    u1.x = x1.x + d1.x; u1.y = x1.y + d1.y; u1.z = x1.z + d1.z; u1.w = x1.w + d1.w;

    float s  = u0.x + u0.y + u0.z + u0.w + u1.x + u1.y + u1.z + u1.w;
    float ss = u0.x*u0.x + u0.y*u0.y + u0.z*u0.z + u0.w*u0.w
             + u1.x*u1.x + u1.y*u1.y + u1.z*u1.z + u1.w*u1.w;
#pragma unroll
    for (int o = 16; o > 0; o >>= 1) {
        s  += __shfl_xor_sync(0xffffffffu, s, o);
        ss += __shfl_xor_sync(0xffffffffu, ss, o);
    }
    const float mean = s * (1.f / DIM);
    const float var  = ss * (1.f / DIM) - mean * mean;
    const float rstd = rsqrtf(var + 1e-6f);

    const float4 gv0 = ((const float4*)g)[lane];
    const float4 gv1 = ((const float4*)g)[32 + lane];
    const float4 bv0 = ((const float4*)b)[lane];
    const float4 bv1 = ((const float4*)b)[32 + lane];

    float4 o0, o1;
    o0.x = (u0.x - mean) * rstd * gv0.x + bv0.x;
    o0.y = (u0.y - mean) * rstd * gv0.y + bv0.y;
    o0.z = (u0.z - mean) * rstd * gv0.z + bv0.z;
    o0.w = (u0.w - mean) * rstd * gv0.w + bv0.w;
    o1.x = (u1.x - mean) * rstd * gv1.x + bv1.x;
    o1.y = (u1.y - mean) * rstd * gv1.y + bv1.y;
    o1.z = (u1.z - mean) * rstd * gv1.z + bv1.z;
    o1.w = (u1.w - mean) * rstd * gv1.w + bv1.w;

    float4* op = (float4*)(out + (size_t)row * DIM);
    op[lane] = o0;
    op[32 + lane] = o1;
}

// ================================================================================
extern "C" void kernel_launch(void* const* d_in, const int* in_sizes, int n_in,
                              void* d_out, int out_size)
{
    (void)in_sizes; (void)n_in; (void)out_size;
    const float* xs  = (const float*)d_in[0];
    const float* h0  = (const float*)d_in[1];
    const float* Wi  = (const float*)d_in[2];
    const float* Wh  = (const float*)d_in[3];
    const float* bh  = (const float*)d_in[4];
    const float* Wg  = (const float*)d_in[5];
    const float* bg  = (const float*)d_in[6];
    const float* g1  = (const float*)d_in[7];
    const float* be1 = (const float*)d_in[8];
    const float* W1  = (const float*)d_in[9];
    const float* b1  = (const float*)d_in[10];
    const float* W2  = (const float*)d_in[11];
    const float* b2  = (const float*)d_in[12];
    const float* g2  = (const float*)d_in[13];
    const float* be2 = (const float*)d_in[14];
    float* out = (float*)d_out;

    float *xg, *ys, *t3, *y, *t1, *t6;
    cudaGetSymbolAddress((void**)&xg, g_xg);
    cudaGetSymbolAddress((void**)&ys, g_ys);
    cudaGetSymbolAddress((void**)&t3, g_t3);
    cudaGetSymbolAddress((void**)&y,  g_y);
    cudaGetSymbolAddress((void**)&t1, g_t1);
    cudaGetSymbolAddress((void**)&t6, g_t6);

    // 1) xg = xs @ Wi
    gemm_kernel<<<dim3(G3 / 128, T_STEPS / 128), 256>>>(xs, Wi, nullptr, xg,
                                                        T_STEPS, G3, DIM, 0, 0);
    // 2) sequential GRU scan -> ys
    scan_kernel<<<NC, SCAN_THREADS>>>(Wh, bh, h0);
    // 3) t3 = relu(ys) @ Wg + bg
    gemm_kernel<<<dim3(DIM / 128, T_STEPS / 128), 256>>>(ys, Wg, bg, t3,
                                                         T_STEPS, DIM, DIM, 1, 0);
    // 4) y = LN(xs + t3) * g1 + be1
    ln_kernel<<<T_STEPS / 8, 256>>>(xs, t3, g1, be1, y);
    // 5) t1 = relu(y @ W1 + b1)
    gemm_kernel<<<dim3(FFN_DIM / 128, T_STEPS / 128), 256>>>(y, W1, b1, t1,
                                                             T_STEPS, FFN_DIM, DIM, 0, 1);
    // 6) t6 = t1 @ W2 + b2
    gemm_kernel<<<dim3(DIM / 128, T_STEPS / 128), 256>>>(t1, W2, b2, t6,
                                                         T_STEPS, DIM, FFN_DIM, 0, 0);
    // 7) out = LN(y + t6) * g2 + be2
    ln_kernel<<<T_STEPS / 8, 256>>>(y, t6, g2, be2, out);
}